// round 2
// baseline (speedup 1.0000x reference)
#include <cuda_runtime.h>
#include <math.h>

// Problem constants
#define LAY 6
#define HH  8
#define DD  512
#define DK  64
#define DFF 2048
#define BB  8
#define SS  1024
#define NN  (BB*SS)          // 8192 rows

// ---------------- scratch (device globals: allocation-free) ----------------
__device__ float g_x  [NN*DD];       // residual stream [N, D]
__device__ float g_q  [BB*HH*SS*DK]; // [b,h,s,k]
__device__ float g_k  [BB*HH*SS*DK];
__device__ float g_v  [BB*HH*SS*DK];
__device__ float g_o  [BB*HH*SS*DK]; // attention output, bhsk
__device__ float g_t  [NN*DD];       // att / ffn-out buffer [N, D]
__device__ float g_ffn[NN*DFF];      // ffn hidden [N, DFF]

// ---------------- positional encoding + input copy ----------------
__global__ void add_pe_kernel(const float* __restrict__ src, float* __restrict__ x) {
    int idx = blockIdx.x * 256 + threadIdx.x;
    if (idx >= NN * DD) return;
    int d = idx & (DD - 1);
    int s = (idx >> 9) & (SS - 1);
    int i = d >> 1;
    // double-precision phase: immune to fast-math sinf range reduction
    double div = exp((double)(2 * i) * (-9.210340371976184 / (double)DD)); // -ln(1e4)/D
    double ang = (double)s * div;
    float pe = (d & 1) ? (float)cos(ang) : (float)sin(ang);
    x[idx] = src[idx] + pe;
}

// ---------------- generic tiled fp32 GEMM ----------------
// C[M,N] = A[M,K] * B[K,N] + bias[N], optional ReLU.
// AMODE 0: row-major, lda=K.   AMODE 1: gather from bhsk tensor (o-concat view).
// BMODE 0: row-major [K,N].    BMODE 1: blocked W[h,d,k] (h=c/64, ld over d = 64).
// OMODE 0: row-major [M,N].    OMODE 1: scatter to bhsk tensor.
template<int AMODE, int BMODE, int OMODE, bool RELU>
__global__ __launch_bounds__(256)
void gemm_kernel(const float* __restrict__ A, const float* __restrict__ B,
                 const float* __restrict__ bias, float* __restrict__ C,
                 int M, int N, int K) {
    const int BM = 128, BN = 128, BK = 8;
    __shared__ float As[BK][BM];
    __shared__ float Bs[BK][BN];

    int bm = blockIdx.y * BM;
    int bn = blockIdx.x * BN;
    int t  = threadIdx.x;
    int tx = t & 15, ty = t >> 4;

    float acc[8][8];
#pragma unroll
    for (int i = 0; i < 8; i++)
#pragma unroll
        for (int j = 0; j < 8; j++) acc[i][j] = 0.f;

    for (int k0 = 0; k0 < K; k0 += BK) {
        // --- load A tile (128x8): thread -> row t/2, 4 k's
        {
            int ar = t >> 1, kq = (t & 1) * 4;
            float4 av;
            if (AMODE == 0) {
                av = *(const float4*)(A + (size_t)(bm + ar) * K + k0 + kq);
            } else {
                int m = bm + ar, kk = k0 + kq;
                av = *(const float4*)(A + ((size_t)(((m >> 10) << 3) + (kk >> 6)) << 16)
                                        + ((m & 1023) << 6) + (kk & 63));
            }
            As[kq + 0][ar] = av.x; As[kq + 1][ar] = av.y;
            As[kq + 2][ar] = av.z; As[kq + 3][ar] = av.w;
        }
        // --- load B tile (8x128): thread -> row t/32, 4 cols
        {
            int br = t >> 5, bc = (t & 31) * 4;
            float4 bv;
            if (BMODE == 0) {
                bv = *(const float4*)(B + (size_t)(k0 + br) * N + bn + bc);
            } else {
                int c = bn + bc, kk = k0 + br;
                bv = *(const float4*)(B + (size_t)(c >> 6) * (DD * DK) + (size_t)kk * DK + (c & 63));
            }
            *(float4*)&Bs[br][bc] = bv;
        }
        __syncthreads();
#pragma unroll
        for (int kk = 0; kk < BK; kk++) {
            float a[8], b[8];
            *(float4*)(a)     = *(float4*)&As[kk][ty * 4];
            *(float4*)(a + 4) = *(float4*)&As[kk][64 + ty * 4];
            *(float4*)(b)     = *(float4*)&Bs[kk][tx * 4];
            *(float4*)(b + 4) = *(float4*)&Bs[kk][64 + tx * 4];
#pragma unroll
            for (int i = 0; i < 8; i++)
#pragma unroll
                for (int j = 0; j < 8; j++) acc[i][j] += a[i] * b[j];
        }
        __syncthreads();
    }

#pragma unroll
    for (int i = 0; i < 8; i++) {
        int m = bm + ((i < 4) ? (ty * 4 + i) : (64 + ty * 4 + i - 4));
#pragma unroll
        for (int j = 0; j < 8; j++) {
            int c = bn + ((j < 4) ? (tx * 4 + j) : (64 + tx * 4 + j - 4));
            float v = acc[i][j] + bias[c];
            if (RELU) v = fmaxf(v, 0.f);
            if (OMODE == 0) {
                C[(size_t)m * N + c] = v;
            } else {
                C[((size_t)(((m >> 10) << 3) + (c >> 6)) << 16) + ((m & 1023) << 6) + (c & 63)] = v;
            }
        }
    }
}

// ---------------- fused attention (flash-style, fp32) ----------------
// grid (B*H, S/128), 128 threads; each thread owns one query row.
__global__ __launch_bounds__(128)
void attn_kernel(const float* __restrict__ Q, const float* __restrict__ K,
                 const float* __restrict__ V, float* __restrict__ O) {
    int bh = blockIdx.x;
    int qr = blockIdx.y * 128 + threadIdx.x;
    int t  = threadIdx.x;

    const float4* qp = (const float4*)(Q + ((size_t)bh * SS + qr) * DK);
    float4 qv[16];
#pragma unroll
    for (int i = 0; i < 16; i++) {
        float4 v = qp[i];
        v.x *= 0.125f; v.y *= 0.125f; v.z *= 0.125f; v.w *= 0.125f; // 1/sqrt(64)
        qv[i] = v;
    }
    float4 acc[16];
#pragma unroll
    for (int i = 0; i < 16; i++) acc[i] = make_float4(0.f, 0.f, 0.f, 0.f);
    float mval = -3.0e38f, lsum = 0.f;

    __shared__ float4 Ks[32 * 16];
    __shared__ float4 Vs[32 * 16];

    for (int kc = 0; kc < SS; kc += 32) {
        const float4* kg = (const float4*)(K + ((size_t)bh * SS + kc) * DK);
        const float4* vg = (const float4*)(V + ((size_t)bh * SS + kc) * DK);
#pragma unroll
        for (int i = 0; i < 4; i++) {
            Ks[t + 128 * i] = kg[t + 128 * i];
            Vs[t + 128 * i] = vg[t + 128 * i];
        }
        __syncthreads();

        float s[32];
#pragma unroll 4
        for (int j = 0; j < 32; j++) {
            float sx = 0.f, sy = 0.f, sz = 0.f, sw = 0.f;
#pragma unroll
            for (int i = 0; i < 16; i++) {
                float4 kv = Ks[j * 16 + i];
                sx += qv[i].x * kv.x; sy += qv[i].y * kv.y;
                sz += qv[i].z * kv.z; sw += qv[i].w * kv.w;
            }
            s[j] = (sx + sy) + (sz + sw);
        }
        float cmax = s[0];
#pragma unroll
        for (int j = 1; j < 32; j++) cmax = fmaxf(cmax, s[j]);
        float mnew = fmaxf(mval, cmax);
        float corr = __expf(mval - mnew);
        lsum *= corr;
#pragma unroll
        for (int i = 0; i < 16; i++) {
            acc[i].x *= corr; acc[i].y *= corr; acc[i].z *= corr; acc[i].w *= corr;
        }
#pragma unroll 4
        for (int j = 0; j < 32; j++) {
            float p = __expf(s[j] - mnew);
            lsum += p;
#pragma unroll
            for (int i = 0; i < 16; i++) {
                float4 vv = Vs[j * 16 + i];
                acc[i].x += p * vv.x; acc[i].y += p * vv.y;
                acc[i].z += p * vv.z; acc[i].w += p * vv.w;
            }
        }
        mval = mnew;
        __syncthreads();
    }

    float inv = 1.f / lsum;
    float4* op = (float4*)(O + ((size_t)bh * SS + qr) * DK);
#pragma unroll
    for (int i = 0; i < 16; i++) {
        float4 v = acc[i];
        v.x *= inv; v.y *= inv; v.z *= inv; v.w *= inv;
        op[i] = v;
    }
}

// ---------------- LayerNorm (+ optional residual add into x) ----------------
// ADD=true:  xio[n,:] += LN(src[n,:])       (writes xio)
// ADD=false: xio[n,:]  = LN(src[n,:])       (final norm -> d_out)
template<bool ADD>
__global__ __launch_bounds__(128)
void ln_kernel(const float* __restrict__ src, const float* __restrict__ gamma,
               const float* __restrict__ beta, float* __restrict__ xio, float eps) {
    int row = blockIdx.x;
    int t   = threadIdx.x;
    int lane = t & 31, wid = t >> 5;
    const float4* sp = (const float4*)(src + (size_t)row * DD);
    float4 v = sp[t];

    __shared__ float red[4];
    __shared__ float bsum, bvar;

    float s = (v.x + v.y) + (v.z + v.w);
#pragma unroll
    for (int o = 16; o > 0; o >>= 1) s += __shfl_xor_sync(0xffffffffu, s, o);
    if (lane == 0) red[wid] = s;
    __syncthreads();
    if (t == 0) bsum = (red[0] + red[1]) + (red[2] + red[3]);
    __syncthreads();
    float mu = bsum * (1.f / DD);

    float dx = v.x - mu, dy = v.y - mu, dz = v.z - mu, dw = v.w - mu;
    float s2 = (dx * dx + dy * dy) + (dz * dz + dw * dw);
#pragma unroll
    for (int o = 16; o > 0; o >>= 1) s2 += __shfl_xor_sync(0xffffffffu, s2, o);
    if (lane == 0) red[wid] = s2;
    __syncthreads();
    if (t == 0) bvar = (red[0] + red[1]) + (red[2] + red[3]);
    __syncthreads();
    float rstd = rsqrtf(bvar * (1.f / DD) + eps);

    int c = t * 4;
    float4 g = *(const float4*)(gamma + c);
    float4 b = *(const float4*)(beta + c);
    float4 o4;
    o4.x = dx * rstd * g.x + b.x;
    o4.y = dy * rstd * g.y + b.y;
    o4.z = dz * rstd * g.z + b.z;
    o4.w = dw * rstd * g.w + b.w;
    float4* xp = (float4*)(xio + (size_t)row * DD);
    if (ADD) {
        float4 xo = xp[t];
        o4.x += xo.x; o4.y += xo.y; o4.z += xo.z; o4.w += xo.w;
    }
    xp[t] = o4;
}

// ---------------- driver ----------------
extern "C" void kernel_launch(void* const* d_in, const int* in_sizes, int n_in,
                              void* d_out, int out_size) {
    const float* src  = (const float*)d_in[0];
    const float* Wq   = (const float*)d_in[1];
    const float* bq   = (const float*)d_in[2];
    const float* Wk   = (const float*)d_in[3];
    const float* bk   = (const float*)d_in[4];
    const float* Wv   = (const float*)d_in[5];
    const float* bv   = (const float*)d_in[6];
    const float* Wo   = (const float*)d_in[7];
    const float* bo   = (const float*)d_in[8];
    const float* ln1g = (const float*)d_in[9];
    const float* ln1b = (const float*)d_in[10];
    const float* W1   = (const float*)d_in[11];
    const float* b1   = (const float*)d_in[12];
    const float* W2   = (const float*)d_in[13];
    const float* b2   = (const float*)d_in[14];
    const float* ln2g = (const float*)d_in[15];
    const float* ln2b = (const float*)d_in[16];
    const float* lnfg = (const float*)d_in[17];
    const float* lnfb = (const float*)d_in[18];
    float* out = (float*)d_out;

    float *px, *pq, *pk, *pv, *po, *pt, *pf;
    cudaGetSymbolAddress((void**)&px, g_x);
    cudaGetSymbolAddress((void**)&pq, g_q);
    cudaGetSymbolAddress((void**)&pk, g_k);
    cudaGetSymbolAddress((void**)&pv, g_v);
    cudaGetSymbolAddress((void**)&po, g_o);
    cudaGetSymbolAddress((void**)&pt, g_t);
    cudaGetSymbolAddress((void**)&pf, g_ffn);

    add_pe_kernel<<<(NN * DD + 255) / 256, 256>>>(src, px);

    dim3 gProj(DD / 128, NN / 128);      // N=512
    dim3 gFfn1(DFF / 128, NN / 128);     // N=2048
    dim3 gAttn(BB * HH, SS / 128);

    for (int l = 0; l < LAY; l++) {
        const float* wq = Wq + (size_t)l * HH * DD * DK;
        const float* wk = Wk + (size_t)l * HH * DD * DK;
        const float* wv = Wv + (size_t)l * HH * DD * DK;
        const float* wo = Wo + (size_t)l * HH * DK * DD;
        const float* w1 = W1 + (size_t)l * DD * DFF;
        const float* w2 = W2 + (size_t)l * DFF * DD;

        // QKV projections: A row-major, B blocked [h,d,k], out bhsk
        gemm_kernel<0, 1, 1, false><<<gProj, 256>>>(px, wq, bq + l * HH * DK, pq, NN, DD, DD);
        gemm_kernel<0, 1, 1, false><<<gProj, 256>>>(px, wk, bk + l * HH * DK, pk, NN, DD, DD);
        gemm_kernel<0, 1, 1, false><<<gProj, 256>>>(px, wv, bv + l * HH * DK, pv, NN, DD, DD);

        attn_kernel<<<gAttn, 128>>>(pq, pk, pv, po);

        // O-projection: A gathered from bhsk, B row-major, out row-major
        gemm_kernel<1, 0, 0, false><<<gProj, 256>>>(po, wo, bo + l * DD, pt, NN, DD, DD);
        ln_kernel<true><<<NN, 128>>>(pt, ln1g + l * DD, ln1b + l * DD, px, 1e-5f);

        // FFN
        gemm_kernel<0, 0, 0, true ><<<gFfn1, 256>>>(px, w1, b1 + l * DFF, pf, NN, DFF, DD);
        gemm_kernel<0, 0, 0, false><<<gProj, 256>>>(pf, w2, b2 + l * DD, pt, NN, DD, DFF);
        ln_kernel<true><<<NN, 128>>>(pt, ln2g + l * DD, ln2b + l * DD, px, 1e-5f);
    }

    ln_kernel<false><<<NN, 128>>>(px, lnfg, lnfb, out, 1e-6f);
}

// round 4
// speedup vs baseline: 1.3559x; 1.3559x over previous
#include <cuda_runtime.h>
#include <cuda_bf16.h>
#include <math.h>
#include <stdint.h>

// Problem constants
#define LAY 6
#define HH  8
#define DD  512
#define DK  64
#define DFF 2048
#define BB  8
#define SS  1024
#define NN  (BB*SS)          // 8192 rows

// ---------------- scratch (device globals: allocation-free) ----------------
__device__ float g_x  [NN*DD];
__device__ float g_q  [BB*HH*SS*DK];
__device__ float g_k  [BB*HH*SS*DK];
__device__ float g_v  [BB*HH*SS*DK];
__device__ float g_o  [BB*HH*SS*DK];
__device__ float g_t  [NN*DD];
__device__ float g_ffn[NN*DFF];

// pre-split weights: per 128n x 64k tile: 8192 bf16 hi + 8192 bf16 lo,
// stored [n&127][k&63] row-major (B^T layout = mma "col" operand layout)
#define TILE_ELEMS 16384
__device__ __nv_bfloat16 g_wq_s[LAY*4*8*TILE_ELEMS];
__device__ __nv_bfloat16 g_wk_s[LAY*4*8*TILE_ELEMS];
__device__ __nv_bfloat16 g_wv_s[LAY*4*8*TILE_ELEMS];
__device__ __nv_bfloat16 g_wo_s[LAY*4*8*TILE_ELEMS];
__device__ __nv_bfloat16 g_w1_s[LAY*16*8*TILE_ELEMS];
__device__ __nv_bfloat16 g_w2_s[LAY*4*32*TILE_ELEMS];

// ---------------- PTX helpers (portable sm_80+ tensor path) ----------------
__device__ __forceinline__ uint32_t smem_u32(const void* p) {
    uint32_t a;
    asm("{ .reg .u64 t; cvta.to.shared.u64 t, %1; cvt.u32.u64 %0, t; }" : "=r"(a) : "l"(p));
    return a;
}
#define LDSM4(r, a) \
    asm volatile("ldmatrix.sync.aligned.m8n8.x4.shared.b16 {%0,%1,%2,%3}, [%4];" \
        : "=r"((r)[0]), "=r"((r)[1]), "=r"((r)[2]), "=r"((r)[3]) : "r"(a))
#define MMA_BF16(d, a, b0, b1) \
    asm volatile("mma.sync.aligned.m16n8k16.row.col.f32.bf16.bf16.f32 " \
        "{%0,%1,%2,%3}, {%4,%5,%6,%7}, {%8,%9}, {%0,%1,%2,%3};" \
        : "+f"((d)[0]), "+f"((d)[1]), "+f"((d)[2]), "+f"((d)[3]) \
        : "r"((a)[0]), "r"((a)[1]), "r"((a)[2]), "r"((a)[3]), "r"(b0), "r"(b1))

// ---------------- positional encoding ----------------
__global__ void add_pe_kernel(const float* __restrict__ src, float* __restrict__ x) {
    int idx = blockIdx.x * 256 + threadIdx.x;
    if (idx >= NN * DD) return;
    int d = idx & (DD - 1);
    int s = (idx >> 9) & (SS - 1);
    int i = d >> 1;
    double div = exp((double)(2 * i) * (-9.210340371976184 / (double)DD));
    double ang = (double)s * div;
    float pe = (d & 1) ? (float)cos(ang) : (float)sin(ang);
    x[idx] = src[idx] + pe;
}

// ---------------- weight pre-split into bf16 hi/lo tiles ----------------
// blocked=1: W is [L,H,D,DK] (QKV); blocked=0: W is [L,K,N] row-major.
__global__ void split_w_kernel(const float* __restrict__ W, __nv_bfloat16* __restrict__ out,
                               int K, int N, int blocked) {
    long long idx = (long long)blockIdx.x * 256 + threadIdx.x;
    long long per = (long long)K * N;
    if (idx >= (long long)LAY * per) return;
    int l = (int)(idx / per);
    int r = (int)(idx % per);
    int k = r / N, n = r % N;
    float x;
    if (blocked) x = W[(((size_t)l * HH + (n >> 6)) * DD + k) * DK + (n & 63)];
    else         x = W[((size_t)l * K + k) * N + n];
    size_t tb = ((size_t)(l * (N >> 7) + (n >> 7)) * (K >> 6) + (k >> 6)) * TILE_ELEMS;
    int off = (n & 127) * 64 + (k & 63);
    __nv_bfloat16 hi = __float2bfloat16_rn(x);
    __nv_bfloat16 lo = __float2bfloat16_rn(x - __bfloat162float(hi));
    out[tb + off] = hi;
    out[tb + 8192 + off] = lo;
}

// ---------------- HMMA GEMM (bf16x3, 128x128 tile, BK=32, 2-stage) ----------------
// smem stage (40960 B): A_hi 128x40bf16 @0, A_lo @10240, B_hi @20480, B_lo @30720
#define SA_LO 10240
#define SB_HI 20480
#define STG_SZ 40960
#define SMEM_DYN (2*STG_SZ)

template<int AMODE, int OMODE, bool RELU>
__global__ __launch_bounds__(256)
void hmma_gemm(const float* __restrict__ A, const __nv_bfloat16* __restrict__ Bt,
               const float* __restrict__ bias, float* __restrict__ C,
               int M, int N, int K) {
    extern __shared__ char smbuf[];
    uint32_t sb = smem_u32(smbuf);
    const int t = threadIdx.x, lane = t & 31, wid = t >> 5;
    const int wm = wid & 3, wn = wid >> 2;
    const int bm = blockIdx.y * 128, bn = blockIdx.x * 128;
    const int nk = K >> 5;
    const int ktile_n = K >> 6;

    float acc[2][8][4];
#pragma unroll
    for (int a = 0; a < 2; a++)
#pragma unroll
        for (int b = 0; b < 8; b++)
#pragma unroll
            for (int c = 0; c < 4; c++) acc[a][b][c] = 0.f;

    float4 ar[4];
    uint4  br[4];

    auto GLOAD = [&](int kt) {
#pragma unroll
        for (int r = 0; r < 4; r++) {
            int i = r * 256 + t;
            int row = i >> 3, q = i & 7;
            int kk = kt * 32 + q * 4;
            if (AMODE == 0) {
                ar[r] = *(const float4*)(A + (size_t)(bm + row) * K + kk);
            } else {
                int mm = bm + row;
                ar[r] = *(const float4*)(A + ((size_t)(((mm >> 10) << 3) + (kk >> 6)) << 16)
                                           + ((mm & 1023) << 6) + (kk & 63));
            }
        }
        const char* tb = (const char*)(Bt + ((size_t)blockIdx.x * ktile_n + (kt >> 1)) * TILE_ELEMS);
        int half = kt & 1;
#pragma unroll
        for (int r = 0; r < 4; r++) {
            int i = r * 256 + t;
            int part = i >> 9, j = i & 511;
            int row = j >> 2, ch = j & 3;
            br[r] = *(const uint4*)(tb + part * 16384 + row * 128 + half * 64 + ch * 16);
        }
    };

    auto SSTORE = [&](int buf) {
        char* stg = smbuf + buf * STG_SZ;
#pragma unroll
        for (int r = 0; r < 4; r++) {
            int i = r * 256 + t;
            int row = i >> 3, q = i & 7;
            float4 a = ar[r];
            __nv_bfloat162 h01 = __floats2bfloat162_rn(a.x, a.y);
            __nv_bfloat162 h23 = __floats2bfloat162_rn(a.z, a.w);
            __nv_bfloat162 l01 = __floats2bfloat162_rn(a.x - __bfloat162float(h01.x),
                                                       a.y - __bfloat162float(h01.y));
            __nv_bfloat162 l23 = __floats2bfloat162_rn(a.z - __bfloat162float(h23.x),
                                                       a.w - __bfloat162float(h23.y));
            int off = row * 80 + q * 8;
            *(uint2*)(stg + off)         = make_uint2(*(uint32_t*)&h01, *(uint32_t*)&h23);
            *(uint2*)(stg + SA_LO + off) = make_uint2(*(uint32_t*)&l01, *(uint32_t*)&l23);
        }
#pragma unroll
        for (int r = 0; r < 4; r++) {
            int i = r * 256 + t;
            int part = i >> 9, j = i & 511;
            int row = j >> 2, ch = j & 3;
            *(uint4*)(stg + SB_HI + part * 10240 + row * 80 + ch * 16) = br[r];
        }
    };

    auto COMPUTE = [&](int buf) {
        uint32_t stg = sb + buf * STG_SZ;
#pragma unroll
        for (int kk = 0; kk < 2; kk++) {
            int acol = (kk * 16 + (lane >> 4) * 8) * 2;   // byte offset along k
            uint32_t af[2][2][4];
#pragma unroll
            for (int mt = 0; mt < 2; mt++) {
                uint32_t aaddr = stg + (wm * 32 + mt * 16 + (lane & 15)) * 80 + acol;
                LDSM4(af[mt][0], aaddr);            // A hi
                LDSM4(af[mt][1], aaddr + SA_LO);    // A lo
            }
#pragma unroll
            for (int nt2 = 0; nt2 < 4; nt2++) {
                uint32_t baddr = stg + SB_HI + (wn * 64 + nt2 * 16 + (lane & 15)) * 80 + acol;
                uint32_t bh[4], bl[4];
                LDSM4(bh, baddr);
                LDSM4(bl, baddr + 10240);
#pragma unroll
                for (int mt = 0; mt < 2; mt++) {
                    MMA_BF16(acc[mt][nt2 * 2],     af[mt][0], bh[0], bh[2]);
                    MMA_BF16(acc[mt][nt2 * 2],     af[mt][0], bl[0], bl[2]);
                    MMA_BF16(acc[mt][nt2 * 2],     af[mt][1], bh[0], bh[2]);
                    MMA_BF16(acc[mt][nt2 * 2 + 1], af[mt][0], bh[1], bh[3]);
                    MMA_BF16(acc[mt][nt2 * 2 + 1], af[mt][0], bl[1], bl[3]);
                    MMA_BF16(acc[mt][nt2 * 2 + 1], af[mt][1], bh[1], bh[3]);
                }
            }
        }
    };

    GLOAD(0);
    SSTORE(0);
    __syncthreads();
    for (int kt = 0; kt < nk; kt++) {
        bool more = (kt + 1) < nk;
        if (more) GLOAD(kt + 1);
        COMPUTE(kt & 1);
        if (more) SSTORE((kt + 1) & 1);   // opposite buffer; safe per prev-iter sync
        __syncthreads();
    }

    // epilogue
    const int mrow = lane >> 2, ncol = (lane & 3) * 2;
#pragma unroll
    for (int mt = 0; mt < 2; mt++) {
#pragma unroll
        for (int nt = 0; nt < 8; nt++) {
            int c = bn + wn * 64 + nt * 8 + ncol;
            float2 bi = *(const float2*)(bias + c);
#pragma unroll
            for (int h = 0; h < 2; h++) {
                int m = bm + wm * 32 + mt * 16 + mrow + h * 8;
                float2 v;
                v.x = acc[mt][nt][h * 2 + 0] + bi.x;
                v.y = acc[mt][nt][h * 2 + 1] + bi.y;
                if (RELU) { v.x = fmaxf(v.x, 0.f); v.y = fmaxf(v.y, 0.f); }
                if (OMODE == 0) {
                    *(float2*)(C + (size_t)m * N + c) = v;
                } else {
                    *(float2*)(C + ((size_t)(((m >> 10) << 3) + (c >> 6)) << 16)
                                 + ((m & 1023) << 6) + (c & 63)) = v;
                }
            }
        }
    }
}

// ---------------- fused attention (flash-style, fp32) ----------------
__global__ __launch_bounds__(128)
void attn_kernel(const float* __restrict__ Q, const float* __restrict__ K,
                 const float* __restrict__ V, float* __restrict__ O) {
    int bh = blockIdx.x;
    int qr = blockIdx.y * 128 + threadIdx.x;
    int t  = threadIdx.x;

    const float4* qp = (const float4*)(Q + ((size_t)bh * SS + qr) * DK);
    float4 qv[16];
#pragma unroll
    for (int i = 0; i < 16; i++) {
        float4 v = qp[i];
        v.x *= 0.125f; v.y *= 0.125f; v.z *= 0.125f; v.w *= 0.125f;
        qv[i] = v;
    }
    float4 acc[16];
#pragma unroll
    for (int i = 0; i < 16; i++) acc[i] = make_float4(0.f, 0.f, 0.f, 0.f);
    float mval = -3.0e38f, lsum = 0.f;

    __shared__ float4 Ks[32 * 16];
    __shared__ float4 Vs[32 * 16];

    for (int kc = 0; kc < SS; kc += 32) {
        const float4* kg = (const float4*)(K + ((size_t)bh * SS + kc) * DK);
        const float4* vg = (const float4*)(V + ((size_t)bh * SS + kc) * DK);
#pragma unroll
        for (int i = 0; i < 4; i++) {
            Ks[t + 128 * i] = kg[t + 128 * i];
            Vs[t + 128 * i] = vg[t + 128 * i];
        }
        __syncthreads();

        float s[32];
#pragma unroll 4
        for (int j = 0; j < 32; j++) {
            float sx = 0.f, sy = 0.f, sz = 0.f, sw = 0.f;
#pragma unroll
            for (int i = 0; i < 16; i++) {
                float4 kv = Ks[j * 16 + i];
                sx += qv[i].x * kv.x; sy += qv[i].y * kv.y;
                sz += qv[i].z * kv.z; sw += qv[i].w * kv.w;
            }
            s[j] = (sx + sy) + (sz + sw);
        }
        float cmax = s[0];
#pragma unroll
        for (int j = 1; j < 32; j++) cmax = fmaxf(cmax, s[j]);
        float mnew = fmaxf(mval, cmax);
        float corr = __expf(mval - mnew);
        lsum *= corr;
#pragma unroll
        for (int i = 0; i < 16; i++) {
            acc[i].x *= corr; acc[i].y *= corr; acc[i].z *= corr; acc[i].w *= corr;
        }
#pragma unroll 4
        for (int j = 0; j < 32; j++) {
            float p = __expf(s[j] - mnew);
            lsum += p;
#pragma unroll
            for (int i = 0; i < 16; i++) {
                float4 vv = Vs[j * 16 + i];
                acc[i].x += p * vv.x; acc[i].y += p * vv.y;
                acc[i].z += p * vv.z; acc[i].w += p * vv.w;
            }
        }
        mval = mnew;
        __syncthreads();
    }

    float inv = 1.f / lsum;
    float4* op = (float4*)(O + ((size_t)bh * SS + qr) * DK);
#pragma unroll
    for (int i = 0; i < 16; i++) {
        float4 v = acc[i];
        v.x *= inv; v.y *= inv; v.z *= inv; v.w *= inv;
        op[i] = v;
    }
}

// ---------------- LayerNorm (+ optional residual add) ----------------
template<bool ADD>
__global__ __launch_bounds__(128)
void ln_kernel(const float* __restrict__ src, const float* __restrict__ gamma,
               const float* __restrict__ beta, float* __restrict__ xio, float eps) {
    int row = blockIdx.x;
    int t = threadIdx.x;
    int lane = t & 31, wid = t >> 5;
    const float4* sp = (const float4*)(src + (size_t)row * DD);
    float4 v = sp[t];

    __shared__ float red[4];
    __shared__ float bsum, bvar;

    float s = (v.x + v.y) + (v.z + v.w);
#pragma unroll
    for (int o = 16; o > 0; o >>= 1) s += __shfl_xor_sync(0xffffffffu, s, o);
    if (lane == 0) red[wid] = s;
    __syncthreads();
    if (t == 0) bsum = (red[0] + red[1]) + (red[2] + red[3]);
    __syncthreads();
    float mu = bsum * (1.f / DD);

    float dx = v.x - mu, dy = v.y - mu, dz = v.z - mu, dw = v.w - mu;
    float s2 = (dx * dx + dy * dy) + (dz * dz + dw * dw);
#pragma unroll
    for (int o = 16; o > 0; o >>= 1) s2 += __shfl_xor_sync(0xffffffffu, s2, o);
    if (lane == 0) red[wid] = s2;
    __syncthreads();
    if (t == 0) bvar = (red[0] + red[1]) + (red[2] + red[3]);
    __syncthreads();
    float rstd = rsqrtf(bvar * (1.f / DD) + eps);

    int c = t * 4;
    float4 g = *(const float4*)(gamma + c);
    float4 b = *(const float4*)(beta + c);
    float4 o4;
    o4.x = dx * rstd * g.x + b.x;
    o4.y = dy * rstd * g.y + b.y;
    o4.z = dz * rstd * g.z + b.z;
    o4.w = dw * rstd * g.w + b.w;
    float4* xp = (float4*)(xio + (size_t)row * DD);
    if (ADD) {
        float4 xo = xp[t];
        o4.x += xo.x; o4.y += xo.y; o4.z += xo.z; o4.w += xo.w;
    }
    xp[t] = o4;
}

// ---------------- driver ----------------
extern "C" void kernel_launch(void* const* d_in, const int* in_sizes, int n_in,
                              void* d_out, int out_size) {
    const float* src  = (const float*)d_in[0];
    const float* Wq   = (const float*)d_in[1];
    const float* bq   = (const float*)d_in[2];
    const float* Wk   = (const float*)d_in[3];
    const float* bk   = (const float*)d_in[4];
    const float* Wv   = (const float*)d_in[5];
    const float* bv   = (const float*)d_in[6];
    const float* Wo   = (const float*)d_in[7];
    const float* bo   = (const float*)d_in[8];
    const float* ln1g = (const float*)d_in[9];
    const float* ln1b = (const float*)d_in[10];
    const float* W1   = (const float*)d_in[11];
    const float* b1   = (const float*)d_in[12];
    const float* W2   = (const float*)d_in[13];
    const float* b2   = (const float*)d_in[14];
    const float* ln2g = (const float*)d_in[15];
    const float* ln2b = (const float*)d_in[16];
    const float* lnfg = (const float*)d_in[17];
    const float* lnfb = (const float*)d_in[18];
    float* out = (float*)d_out;

    float *px, *pq, *pk, *pv, *po, *pt, *pf;
    __nv_bfloat16 *wqs, *wks, *wvs, *wos, *w1s, *w2s;
    cudaGetSymbolAddress((void**)&px, g_x);
    cudaGetSymbolAddress((void**)&pq, g_q);
    cudaGetSymbolAddress((void**)&pk, g_k);
    cudaGetSymbolAddress((void**)&pv, g_v);
    cudaGetSymbolAddress((void**)&po, g_o);
    cudaGetSymbolAddress((void**)&pt, g_t);
    cudaGetSymbolAddress((void**)&pf, g_ffn);
    cudaGetSymbolAddress((void**)&wqs, g_wq_s);
    cudaGetSymbolAddress((void**)&wks, g_wk_s);
    cudaGetSymbolAddress((void**)&wvs, g_wv_s);
    cudaGetSymbolAddress((void**)&wos, g_wo_s);
    cudaGetSymbolAddress((void**)&w1s, g_w1_s);
    cudaGetSymbolAddress((void**)&w2s, g_w2_s);

    cudaFuncSetAttribute(hmma_gemm<0,1,false>, cudaFuncAttributeMaxDynamicSharedMemorySize, SMEM_DYN);
    cudaFuncSetAttribute(hmma_gemm<1,0,false>, cudaFuncAttributeMaxDynamicSharedMemorySize, SMEM_DYN);
    cudaFuncSetAttribute(hmma_gemm<0,0,true >, cudaFuncAttributeMaxDynamicSharedMemorySize, SMEM_DYN);
    cudaFuncSetAttribute(hmma_gemm<0,0,false>, cudaFuncAttributeMaxDynamicSharedMemorySize, SMEM_DYN);

    // weight pre-split (runs each replay; deterministic)
    {
        long long tq = (long long)LAY * DD * DD;
        long long t1 = (long long)LAY * DD * DFF;
        int gq = (int)((tq + 255) / 256), g1 = (int)((t1 + 255) / 256);
        split_w_kernel<<<gq, 256>>>(Wq, wqs, DD, DD, 1);
        split_w_kernel<<<gq, 256>>>(Wk, wks, DD, DD, 1);
        split_w_kernel<<<gq, 256>>>(Wv, wvs, DD, DD, 1);
        split_w_kernel<<<gq, 256>>>(Wo, wos, DD, DD, 0);
        split_w_kernel<<<g1, 256>>>(W1, w1s, DD, DFF, 0);
        split_w_kernel<<<g1, 256>>>(W2, w2s, DFF, DD, 0);
    }

    add_pe_kernel<<<(NN * DD + 255) / 256, 256>>>(src, px);

    dim3 gProj(4, 64);    // N=512
    dim3 gFfn1(16, 64);   // N=2048
    dim3 gAttn(BB * HH, SS / 128);

    for (int l = 0; l < LAY; l++) {
        size_t ws_proj = (size_t)l * 4 * 8 * TILE_ELEMS;
        size_t ws_w1   = (size_t)l * 16 * 8 * TILE_ELEMS;
        size_t ws_w2   = (size_t)l * 4 * 32 * TILE_ELEMS;

        hmma_gemm<0,1,false><<<gProj, 256, SMEM_DYN>>>(px, wqs + ws_proj, bq + l * HH * DK, pq, NN, DD, DD);
        hmma_gemm<0,1,false><<<gProj, 256, SMEM_DYN>>>(px, wks + ws_proj, bk + l * HH * DK, pk, NN, DD, DD);
        hmma_gemm<0,1,false><<<gProj, 256, SMEM_DYN>>>(px, wvs + ws_proj, bv + l * HH * DK, pv, NN, DD, DD);

        attn_kernel<<<gAttn, 128>>>(pq, pk, pv, po);

        hmma_gemm<1,0,false><<<gProj, 256, SMEM_DYN>>>(po, wos + ws_proj, bo + l * DD, pt, NN, DD, DD);
        ln_kernel<true><<<NN, 128>>>(pt, ln1g + l * DD, ln1b + l * DD, px, 1e-5f);

        hmma_gemm<0,0,true ><<<gFfn1, 256, SMEM_DYN>>>(px, w1s + ws_w1, b1 + l * DFF, pf, NN, DFF, DD);
        hmma_gemm<0,0,false><<<gProj, 256, SMEM_DYN>>>(pf, w2s + ws_w2, b2 + l * DD, pt, NN, DD, DFF);
        ln_kernel<true><<<NN, 128>>>(pt, ln2g + l * DD, ln2b + l * DD, px, 1e-5f);
    }

    ln_kernel<false><<<NN, 128>>>(px, lnfg, lnfb, out, 1e-6f);
}

// round 7
// speedup vs baseline: 2.0023x; 1.4767x over previous
#include <cuda_runtime.h>
#include <cuda_bf16.h>
#include <math.h>
#include <stdint.h>

// Problem constants
#define LAY 6
#define HH  8
#define DD  512
#define DK  64
#define DFF 2048
#define BB  8
#define SS  1024
#define NN  (BB*SS)          // 8192 rows

// ---------------- scratch (device globals: allocation-free) ----------------
__device__ float g_x  [NN*DD];
__device__ float g_q  [BB*HH*SS*DK];
__device__ float g_k  [BB*HH*SS*DK];
__device__ float g_v  [BB*HH*SS*DK];
__device__ float g_o  [BB*HH*SS*DK];
__device__ float g_t  [NN*DD];
__device__ float g_ffn[NN*DFF];

// pre-split weights: per 128n x 64k tile: 8192 bf16 hi + 8192 bf16 lo,
// stored [n&127][k&63] row-major (B^T layout = mma "col" operand layout)
#define TILE_ELEMS 16384
__device__ __nv_bfloat16 g_wq_s[LAY*4*8*TILE_ELEMS];
__device__ __nv_bfloat16 g_wk_s[LAY*4*8*TILE_ELEMS];
__device__ __nv_bfloat16 g_wv_s[LAY*4*8*TILE_ELEMS];
__device__ __nv_bfloat16 g_wo_s[LAY*4*8*TILE_ELEMS];
__device__ __nv_bfloat16 g_w1_s[LAY*16*8*TILE_ELEMS];
__device__ __nv_bfloat16 g_w2_s[LAY*4*32*TILE_ELEMS];

// ---------------- PTX helpers ----------------
__device__ __forceinline__ uint32_t smem_u32(const void* p) {
    uint32_t a;
    asm("{ .reg .u64 t; cvta.to.shared.u64 t, %1; cvt.u32.u64 %0, t; }" : "=r"(a) : "l"(p));
    return a;
}
#define LDSM4(r, a) \
    asm volatile("ldmatrix.sync.aligned.m8n8.x4.shared.b16 {%0,%1,%2,%3}, [%4];" \
        : "=r"((r)[0]), "=r"((r)[1]), "=r"((r)[2]), "=r"((r)[3]) : "r"(a))
#define LDSM4T(r, a) \
    asm volatile("ldmatrix.sync.aligned.m8n8.x4.trans.shared.b16 {%0,%1,%2,%3}, [%4];" \
        : "=r"((r)[0]), "=r"((r)[1]), "=r"((r)[2]), "=r"((r)[3]) : "r"(a))
#define MMA_BF16(d, a, b0, b1) \
    asm volatile("mma.sync.aligned.m16n8k16.row.col.f32.bf16.bf16.f32 " \
        "{%0,%1,%2,%3}, {%4,%5,%6,%7}, {%8,%9}, {%0,%1,%2,%3};" \
        : "+f"((d)[0]), "+f"((d)[1]), "+f"((d)[2]), "+f"((d)[3]) \
        : "r"((a)[0]), "r"((a)[1]), "r"((a)[2]), "r"((a)[3]), "r"(b0), "r"(b1))

// fast e^x on the FMA pipe (x <= 0 path; ~1.5e-7 rel error)
__device__ __forceinline__ float fexp(float x) {
    float t = x * 1.44269504f;
    t = fmaxf(t, -126.0f);
    float i = rintf(t);
    float f = t - i;
    float p =       1.54035304e-4f;
    p = fmaf(p, f, 1.33335581e-3f);
    p = fmaf(p, f, 9.61812910e-3f);
    p = fmaf(p, f, 5.55041086e-2f);
    p = fmaf(p, f, 2.40226507e-1f);
    p = fmaf(p, f, 6.93147182e-1f);
    p = fmaf(p, f, 1.0f);
    return p * __int_as_float(((int)i + 127) << 23);
}

__device__ __forceinline__ void split2(float a, float b, uint32_t& hi, uint32_t& lo) {
    __nv_bfloat162 h = __floats2bfloat162_rn(a, b);
    __nv_bfloat162 l = __floats2bfloat162_rn(a - __bfloat162float(h.x),
                                             b - __bfloat162float(h.y));
    hi = *(uint32_t*)&h;
    lo = *(uint32_t*)&l;
}

// ---------------- positional encoding ----------------
__global__ void add_pe_kernel(const float* __restrict__ src, float* __restrict__ x) {
    int idx = blockIdx.x * 256 + threadIdx.x;
    if (idx >= NN * DD) return;
    int d = idx & (DD - 1);
    int s = (idx >> 9) & (SS - 1);
    int i = d >> 1;
    double div = exp((double)(2 * i) * (-9.210340371976184 / (double)DD));
    double ang = (double)s * div;
    float pe = (d & 1) ? (float)cos(ang) : (float)sin(ang);
    x[idx] = src[idx] + pe;
}

// ---------------- weight pre-split (smem transpose, coalesced I/O) ----------------
// one CTA per 128n x 64k tile; grid = L*(N/128)*(K/64), kt fastest.
__global__ __launch_bounds__(256)
void split_w_kernel(const float* __restrict__ W, __nv_bfloat16* __restrict__ out,
                    int K, int N, int blocked) {
    __shared__ float s[128][65];
    int tile = blockIdx.x;
    int kt = tile % (K >> 6);
    int rest = tile / (K >> 6);
    int nt = rest % (N >> 7);
    int l = rest / (N >> 7);
    int n0 = nt << 7, k0 = kt << 6;
    int t = threadIdx.x;
#pragma unroll
    for (int r = 0; r < 32; r++) {
        int i = r * 256 + t;
        int k = i >> 7, n = i & 127;
        float x;
        if (blocked) x = W[(((size_t)l * HH + ((n0 + n) >> 6)) * DD + k0 + k) * DK + ((n0 + n) & 63)];
        else         x = W[((size_t)l * K + k0 + k) * N + n0 + n];
        s[n][k] = x;
    }
    __syncthreads();
    uint32_t* oh = (uint32_t*)(out + (size_t)tile * TILE_ELEMS);
    uint32_t* ol = oh + 4096;
#pragma unroll
    for (int r = 0; r < 16; r++) {
        int i = r * 256 + t;
        int n = i >> 5, k = (i & 31) << 1;
        uint32_t hi, lo;
        split2(s[n][k], s[n][k + 1], hi, lo);
        oh[n * 32 + (k >> 1)] = hi;
        ol[n * 32 + (k >> 1)] = lo;
    }
}

// ---------------- HMMA GEMM (bf16x3, 128x128 tile, BK=32, 2-stage) ----------------
#define SA_LO 10240
#define SB_HI 20480
#define STG_SZ 40960
#define SMEM_DYN (2*STG_SZ)

template<int AMODE, int OMODE, bool RELU>
__global__ __launch_bounds__(256)
void hmma_gemm(const float* __restrict__ A, const __nv_bfloat16* __restrict__ Bt,
               const float* __restrict__ bias, float* __restrict__ C,
               int M, int N, int K) {
    extern __shared__ char smbuf[];
    uint32_t sb = smem_u32(smbuf);
    const int t = threadIdx.x, lane = t & 31, wid = t >> 5;
    const int wm = wid & 3, wn = wid >> 2;
    const int bm = blockIdx.y * 128, bn = blockIdx.x * 128;
    const int nk = K >> 5;
    const int ktile_n = K >> 6;

    float acc[2][8][4];
#pragma unroll
    for (int a = 0; a < 2; a++)
#pragma unroll
        for (int b = 0; b < 8; b++)
#pragma unroll
            for (int c = 0; c < 4; c++) acc[a][b][c] = 0.f;

    float4 ar[4];
    uint4  br[4];

    auto GLOAD = [&](int kt) {
#pragma unroll
        for (int r = 0; r < 4; r++) {
            int i = r * 256 + t;
            int row = i >> 3, q = i & 7;
            int kk = kt * 32 + q * 4;
            if (AMODE == 0) {
                ar[r] = *(const float4*)(A + (size_t)(bm + row) * K + kk);
            } else {
                int mm = bm + row;
                ar[r] = *(const float4*)(A + ((size_t)(((mm >> 10) << 3) + (kk >> 6)) << 16)
                                           + ((mm & 1023) << 6) + (kk & 63));
            }
        }
        const char* tb = (const char*)(Bt + ((size_t)blockIdx.x * ktile_n + (kt >> 1)) * TILE_ELEMS);
        int half = kt & 1;
#pragma unroll
        for (int r = 0; r < 4; r++) {
            int i = r * 256 + t;
            int part = i >> 9, j = i & 511;
            int row = j >> 2, ch = j & 3;
            br[r] = *(const uint4*)(tb + part * 16384 + row * 128 + half * 64 + ch * 16);
        }
    };

    auto SSTORE = [&](int buf) {
        char* stg = smbuf + buf * STG_SZ;
#pragma unroll
        for (int r = 0; r < 4; r++) {
            int i = r * 256 + t;
            int row = i >> 3, q = i & 7;
            float4 a = ar[r];
            uint32_t h01, l01, h23, l23;
            split2(a.x, a.y, h01, l01);
            split2(a.z, a.w, h23, l23);
            int off = row * 80 + q * 8;
            *(uint2*)(stg + off)         = make_uint2(h01, h23);
            *(uint2*)(stg + SA_LO + off) = make_uint2(l01, l23);
        }
#pragma unroll
        for (int r = 0; r < 4; r++) {
            int i = r * 256 + t;
            int part = i >> 9, j = i & 511;
            int row = j >> 2, ch = j & 3;
            *(uint4*)(stg + SB_HI + part * 10240 + row * 80 + ch * 16) = br[r];
        }
    };

    auto COMPUTE = [&](int buf) {
        uint32_t stg = sb + buf * STG_SZ;
#pragma unroll
        for (int kk = 0; kk < 2; kk++) {
            int acol = (kk * 16 + (lane >> 4) * 8) * 2;
            uint32_t af[2][2][4];
#pragma unroll
            for (int mt = 0; mt < 2; mt++) {
                uint32_t aaddr = stg + (wm * 32 + mt * 16 + (lane & 15)) * 80 + acol;
                LDSM4(af[mt][0], aaddr);
                LDSM4(af[mt][1], aaddr + SA_LO);
            }
#pragma unroll
            for (int nt2 = 0; nt2 < 4; nt2++) {
                uint32_t baddr = stg + SB_HI + (wn * 64 + nt2 * 16 + (lane & 15)) * 80 + acol;
                uint32_t bh[4], bl[4];
                LDSM4(bh, baddr);
                LDSM4(bl, baddr + 10240);
#pragma unroll
                for (int mt = 0; mt < 2; mt++) {
                    MMA_BF16(acc[mt][nt2 * 2],     af[mt][0], bh[0], bh[2]);
                    MMA_BF16(acc[mt][nt2 * 2],     af[mt][0], bl[0], bl[2]);
                    MMA_BF16(acc[mt][nt2 * 2],     af[mt][1], bh[0], bh[2]);
                    MMA_BF16(acc[mt][nt2 * 2 + 1], af[mt][0], bh[1], bh[3]);
                    MMA_BF16(acc[mt][nt2 * 2 + 1], af[mt][0], bl[1], bl[3]);
                    MMA_BF16(acc[mt][nt2 * 2 + 1], af[mt][1], bh[1], bh[3]);
                }
            }
        }
    };

    GLOAD(0);
    SSTORE(0);
    __syncthreads();
    for (int kt = 0; kt < nk; kt++) {
        bool more = (kt + 1) < nk;
        if (more) GLOAD(kt + 1);
        COMPUTE(kt & 1);
        if (more) SSTORE((kt + 1) & 1);
        __syncthreads();
    }

    const int mrow = lane >> 2, ncol = (lane & 3) * 2;
#pragma unroll
    for (int mt = 0; mt < 2; mt++) {
#pragma unroll
        for (int nt = 0; nt < 8; nt++) {
            int c = bn + wn * 64 + nt * 8 + ncol;
            float2 bi = *(const float2*)(bias + c);
#pragma unroll
            for (int h = 0; h < 2; h++) {
                int m = bm + wm * 32 + mt * 16 + mrow + h * 8;
                float2 v;
                v.x = acc[mt][nt][h * 2 + 0] + bi.x;
                v.y = acc[mt][nt][h * 2 + 1] + bi.y;
                if (RELU) { v.x = fmaxf(v.x, 0.f); v.y = fmaxf(v.y, 0.f); }
                if (OMODE == 0) {
                    *(float2*)(C + (size_t)m * N + c) = v;
                } else {
                    *(float2*)(C + ((size_t)(((m >> 10) << 3) + (c >> 6)) << 16)
                                 + ((m & 1023) << 6) + (c & 63)) = v;
                }
            }
        }
    }
}

// ---------------- HMMA flash attention (bf16x3, exp on FMA pipe) ----------------
// grid (B*H, S/128), 256 threads (8 warps x 16 q-rows). kv chunk = 64.
// smem: QHI/QLO 128x72bf16, KHI/KLO 64x72, VHI/VLO 64x72 (stride 144B).
#define AQ_HI 0
#define AQ_LO 18432
#define AK_HI 36864
#define AK_LO 46080
#define AV_HI 55296
#define AV_LO 64512
#define ATT_SMEM 73728

__global__ __launch_bounds__(256)
void attn_hmma(const float* __restrict__ Q, const float* __restrict__ K,
               const float* __restrict__ V, float* __restrict__ O) {
    extern __shared__ char smbuf[];
    uint32_t sb = smem_u32(smbuf);
    const int t = threadIdx.x, lane = t & 31, w = t >> 5;
    const int bh = blockIdx.x;
    const int qbase = blockIdx.y * 128;

    // ---- load Q tile, scale by 1/sqrt(dk), split to smem ----
#pragma unroll
    for (int r = 0; r < 8; r++) {
        int j = r * 256 + t;
        int row = j >> 4, cq = (j & 15) << 2;
        float4 a = *(const float4*)(Q + ((size_t)bh * SS + qbase + row) * DK + cq);
        a.x *= 0.125f; a.y *= 0.125f; a.z *= 0.125f; a.w *= 0.125f;
        uint32_t h01, l01, h23, l23;
        split2(a.x, a.y, h01, l01);
        split2(a.z, a.w, h23, l23);
        int off = row * 144 + cq * 2;
        *(uint2*)(smbuf + AQ_HI + off) = make_uint2(h01, h23);
        *(uint2*)(smbuf + AQ_LO + off) = make_uint2(l01, l23);
    }
    __syncthreads();

    // ---- hoist Q fragments to registers (reused for all 16 chunks) ----
    uint32_t qh[4][4], ql[4][4];
#pragma unroll
    for (int kb = 0; kb < 4; kb++) {
        uint32_t addr = sb + (w * 16 + (lane & 15)) * 144 + (kb * 16 + (lane >> 4) * 8) * 2;
        LDSM4(qh[kb], addr + AQ_HI);
        LDSM4(ql[kb], addr + AQ_LO);
    }

    float o[8][4];
#pragma unroll
    for (int i = 0; i < 8; i++)
#pragma unroll
        for (int j = 0; j < 4; j++) o[i][j] = 0.f;
    float m0 = -1.0e30f, m1 = -1.0e30f, l0 = 0.f, l1 = 0.f;

    for (int kc = 0; kc < SS; kc += 64) {
        __syncthreads();   // prior chunk's MMAs done reading K/V smem
        // ---- load K,V chunk, split to smem ----
#pragma unroll
        for (int r = 0; r < 4; r++) {
            int j = r * 256 + t;
            int row = j >> 4, cq = (j & 15) << 2;
            int off = row * 144 + cq * 2;
            float4 a = *(const float4*)(K + ((size_t)bh * SS + kc + row) * DK + cq);
            uint32_t h01, l01, h23, l23;
            split2(a.x, a.y, h01, l01);
            split2(a.z, a.w, h23, l23);
            *(uint2*)(smbuf + AK_HI + off) = make_uint2(h01, h23);
            *(uint2*)(smbuf + AK_LO + off) = make_uint2(l01, l23);
            float4 b = *(const float4*)(V + ((size_t)bh * SS + kc + row) * DK + cq);
            split2(b.x, b.y, h01, l01);
            split2(b.z, b.w, h23, l23);
            *(uint2*)(smbuf + AV_HI + off) = make_uint2(h01, h23);
            *(uint2*)(smbuf + AV_LO + off) = make_uint2(l01, l23);
        }
        __syncthreads();

        // ---- S = Q K^T (3-term split), fp32 frags ----
        float s[8][4];
#pragma unroll
        for (int i = 0; i < 8; i++)
#pragma unroll
            for (int j = 0; j < 4; j++) s[i][j] = 0.f;
#pragma unroll
        for (int kvb = 0; kvb < 4; kvb++) {
#pragma unroll
            for (int kb = 0; kb < 4; kb++) {
                uint32_t addr = sb + (kvb * 16 + (lane & 15)) * 144 + (kb * 16 + (lane >> 4) * 8) * 2;
                uint32_t kh[4], kl[4];
                LDSM4(kh, addr + AK_HI);
                LDSM4(kl, addr + AK_LO);
                MMA_BF16(s[kvb * 2],     qh[kb], kh[0], kh[2]);
                MMA_BF16(s[kvb * 2],     qh[kb], kl[0], kl[2]);
                MMA_BF16(s[kvb * 2],     ql[kb], kh[0], kh[2]);
                MMA_BF16(s[kvb * 2 + 1], qh[kb], kh[1], kh[3]);
                MMA_BF16(s[kvb * 2 + 1], qh[kb], kl[1], kl[3]);
                MMA_BF16(s[kvb * 2 + 1], ql[kb], kh[1], kh[3]);
            }
        }

        // ---- online softmax (row pair per lane) ----
        float cm0 = -1.0e30f, cm1 = -1.0e30f;
#pragma unroll
        for (int nb = 0; nb < 8; nb++) {
            cm0 = fmaxf(cm0, fmaxf(s[nb][0], s[nb][1]));
            cm1 = fmaxf(cm1, fmaxf(s[nb][2], s[nb][3]));
        }
        cm0 = fmaxf(cm0, __shfl_xor_sync(0xffffffffu, cm0, 1));
        cm0 = fmaxf(cm0, __shfl_xor_sync(0xffffffffu, cm0, 2));
        cm1 = fmaxf(cm1, __shfl_xor_sync(0xffffffffu, cm1, 1));
        cm1 = fmaxf(cm1, __shfl_xor_sync(0xffffffffu, cm1, 2));
        float m0n = fmaxf(m0, cm0), m1n = fmaxf(m1, cm1);
        float c0 = fexp(m0 - m0n), c1 = fexp(m1 - m1n);
#pragma unroll
        for (int nb = 0; nb < 8; nb++) {
            o[nb][0] *= c0; o[nb][1] *= c0;
            o[nb][2] *= c1; o[nb][3] *= c1;
        }
        float ls0 = 0.f, ls1 = 0.f;
#pragma unroll
        for (int nb = 0; nb < 8; nb++) {
            s[nb][0] = fexp(s[nb][0] - m0n);
            s[nb][1] = fexp(s[nb][1] - m0n);
            s[nb][2] = fexp(s[nb][2] - m1n);
            s[nb][3] = fexp(s[nb][3] - m1n);
            ls0 += s[nb][0] + s[nb][1];
            ls1 += s[nb][2] + s[nb][3];
        }
        ls0 += __shfl_xor_sync(0xffffffffu, ls0, 1);
        ls0 += __shfl_xor_sync(0xffffffffu, ls0, 2);
        ls1 += __shfl_xor_sync(0xffffffffu, ls1, 1);
        ls1 += __shfl_xor_sync(0xffffffffu, ls1, 2);
        l0 = l0 * c0 + ls0;
        l1 = l1 * c1 + ls1;
        m0 = m0n; m1 = m1n;

        // ---- O += P V (3-term split); P frags built in registers ----
#pragma unroll
        for (int kb = 0; kb < 4; kb++) {
            uint32_t ph[4], pl[4];
            split2(s[2 * kb][0],     s[2 * kb][1],     ph[0], pl[0]);
            split2(s[2 * kb][2],     s[2 * kb][3],     ph[1], pl[1]);
            split2(s[2 * kb + 1][0], s[2 * kb + 1][1], ph[2], pl[2]);
            split2(s[2 * kb + 1][2], s[2 * kb + 1][3], ph[3], pl[3]);
#pragma unroll
            for (int db = 0; db < 4; db++) {
                uint32_t addr = sb + (kb * 16 + (lane & 15)) * 144 + (db * 16 + (lane >> 4) * 8) * 2;
                uint32_t vh[4], vl[4];
                LDSM4T(vh, addr + AV_HI);
                LDSM4T(vl, addr + AV_LO);
                MMA_BF16(o[db * 2],     ph, vh[0], vh[1]);
                MMA_BF16(o[db * 2],     ph, vl[0], vl[1]);
                MMA_BF16(o[db * 2],     pl, vh[0], vh[1]);
                MMA_BF16(o[db * 2 + 1], ph, vh[2], vh[3]);
                MMA_BF16(o[db * 2 + 1], ph, vl[2], vl[3]);
                MMA_BF16(o[db * 2 + 1], pl, vh[2], vh[3]);
            }
        }
    }

    // ---- normalize and write ----
    float inv0 = 1.f / l0, inv1 = 1.f / l1;
    int r0 = qbase + w * 16 + (lane >> 2);
    int c0c = (lane & 3) * 2;
#pragma unroll
    for (int db = 0; db < 8; db++) {
        int c = db * 8 + c0c;
        *(float2*)(O + ((size_t)bh * SS + r0) * DK + c)
            = make_float2(o[db][0] * inv0, o[db][1] * inv0);
        *(float2*)(O + ((size_t)bh * SS + r0 + 8) * DK + c)
            = make_float2(o[db][2] * inv1, o[db][3] * inv1);
    }
}

// ---------------- LayerNorm (+ optional residual add) ----------------
template<bool ADD>
__global__ __launch_bounds__(128)
void ln_kernel(const float* __restrict__ src, const float* __restrict__ gamma,
               const float* __restrict__ beta, float* __restrict__ xio, float eps) {
    int row = blockIdx.x;
    int t = threadIdx.x;
    int lane = t & 31, wid = t >> 5;
    const float4* sp = (const float4*)(src + (size_t)row * DD);
    float4 v = sp[t];

    __shared__ float red[4];
    __shared__ float bsum, bvar;

    float s = (v.x + v.y) + (v.z + v.w);
#pragma unroll
    for (int o = 16; o > 0; o >>= 1) s += __shfl_xor_sync(0xffffffffu, s, o);
    if (lane == 0) red[wid] = s;
    __syncthreads();
    if (t == 0) bsum = (red[0] + red[1]) + (red[2] + red[3]);
    __syncthreads();
    float mu = bsum * (1.f / DD);

    float dx = v.x - mu, dy = v.y - mu, dz = v.z - mu, dw = v.w - mu;
    float s2 = (dx * dx + dy * dy) + (dz * dz + dw * dw);
#pragma unroll
    for (int o = 16; o > 0; o >>= 1) s2 += __shfl_xor_sync(0xffffffffu, s2, o);
    if (lane == 0) red[wid] = s2;
    __syncthreads();
    if (t == 0) bvar = (red[0] + red[1]) + (red[2] + red[3]);
    __syncthreads();
    float rstd = rsqrtf(bvar * (1.f / DD) + eps);

    int c = t * 4;
    float4 g = *(const float4*)(gamma + c);
    float4 b = *(const float4*)(beta + c);
    float4 o4;
    o4.x = dx * rstd * g.x + b.x;
    o4.y = dy * rstd * g.y + b.y;
    o4.z = dz * rstd * g.z + b.z;
    o4.w = dw * rstd * g.w + b.w;
    float4* xp = (float4*)(xio + (size_t)row * DD);
    if (ADD) {
        float4 xo = xp[t];
        o4.x += xo.x; o4.y += xo.y; o4.z += xo.z; o4.w += xo.w;
    }
    xp[t] = o4;
}

// ---------------- driver ----------------
extern "C" void kernel_launch(void* const* d_in, const int* in_sizes, int n_in,
                              void* d_out, int out_size) {
    const float* src  = (const float*)d_in[0];
    const float* Wq   = (const float*)d_in[1];
    const float* bq   = (const float*)d_in[2];
    const float* Wk   = (const float*)d_in[3];
    const float* bk   = (const float*)d_in[4];
    const float* Wv   = (const float*)d_in[5];
    const float* bv   = (const float*)d_in[6];
    const float* Wo   = (const float*)d_in[7];
    const float* bo   = (const float*)d_in[8];
    const float* ln1g = (const float*)d_in[9];
    const float* ln1b = (const float*)d_in[10];
    const float* W1   = (const float*)d_in[11];
    const float* b1   = (const float*)d_in[12];
    const float* W2   = (const float*)d_in[13];
    const float* b2   = (const float*)d_in[14];
    const float* ln2g = (const float*)d_in[15];
    const float* ln2b = (const float*)d_in[16];
    const float* lnfg = (const float*)d_in[17];
    const float* lnfb = (const float*)d_in[18];
    float* out = (float*)d_out;

    float *px, *pq, *pk, *pv, *po, *pt, *pf;
    __nv_bfloat16 *wqs, *wks, *wvs, *wos, *w1s, *w2s;
    cudaGetSymbolAddress((void**)&px, g_x);
    cudaGetSymbolAddress((void**)&pq, g_q);
    cudaGetSymbolAddress((void**)&pk, g_k);
    cudaGetSymbolAddress((void**)&pv, g_v);
    cudaGetSymbolAddress((void**)&po, g_o);
    cudaGetSymbolAddress((void**)&pt, g_t);
    cudaGetSymbolAddress((void**)&pf, g_ffn);
    cudaGetSymbolAddress((void**)&wqs, g_wq_s);
    cudaGetSymbolAddress((void**)&wks, g_wk_s);
    cudaGetSymbolAddress((void**)&wvs, g_wv_s);
    cudaGetSymbolAddress((void**)&wos, g_wo_s);
    cudaGetSymbolAddress((void**)&w1s, g_w1_s);
    cudaGetSymbolAddress((void**)&w2s, g_w2_s);

    cudaFuncSetAttribute(hmma_gemm<0,1,false>, cudaFuncAttributeMaxDynamicSharedMemorySize, SMEM_DYN);
    cudaFuncSetAttribute(hmma_gemm<1,0,false>, cudaFuncAttributeMaxDynamicSharedMemorySize, SMEM_DYN);
    cudaFuncSetAttribute(hmma_gemm<0,0,true >, cudaFuncAttributeMaxDynamicSharedMemorySize, SMEM_DYN);
    cudaFuncSetAttribute(hmma_gemm<0,0,false>, cudaFuncAttributeMaxDynamicSharedMemorySize, SMEM_DYN);
    cudaFuncSetAttribute(attn_hmma, cudaFuncAttributeMaxDynamicSharedMemorySize, ATT_SMEM);

    // weight pre-split (tile-transpose, coalesced)
    split_w_kernel<<<LAY * 4 * 8, 256>>>(Wq, wqs, DD, DD, 1);
    split_w_kernel<<<LAY * 4 * 8, 256>>>(Wk, wks, DD, DD, 1);
    split_w_kernel<<<LAY * 4 * 8, 256>>>(Wv, wvs, DD, DD, 1);
    split_w_kernel<<<LAY * 4 * 8, 256>>>(Wo, wos, DD, DD, 0);
    split_w_kernel<<<LAY * 16 * 8, 256>>>(W1, w1s, DD, DFF, 0);
    split_w_kernel<<<LAY * 4 * 32, 256>>>(W2, w2s, DFF, DD, 0);

    add_pe_kernel<<<(NN * DD + 255) / 256, 256>>>(src, px);

    dim3 gProj(4, 64);    // N=512
    dim3 gFfn1(16, 64);   // N=2048
    dim3 gAttn(BB * HH, SS / 128);

    for (int l = 0; l < LAY; l++) {
        size_t ws_proj = (size_t)l * 4 * 8 * TILE_ELEMS;
        size_t ws_w1   = (size_t)l * 16 * 8 * TILE_ELEMS;
        size_t ws_w2   = (size_t)l * 4 * 32 * TILE_ELEMS;

        hmma_gemm<0,1,false><<<gProj, 256, SMEM_DYN>>>(px, wqs + ws_proj, bq + l * HH * DK, pq, NN, DD, DD);
        hmma_gemm<0,1,false><<<gProj, 256, SMEM_DYN>>>(px, wks + ws_proj, bk + l * HH * DK, pk, NN, DD, DD);
        hmma_gemm<0,1,false><<<gProj, 256, SMEM_DYN>>>(px, wvs + ws_proj, bv + l * HH * DK, pv, NN, DD, DD);

        attn_hmma<<<gAttn, 256, ATT_SMEM>>>(pq, pk, pv, po);

        hmma_gemm<1,0,false><<<gProj, 256, SMEM_DYN>>>(po, wos + ws_proj, bo + l * DD, pt, NN, DD, DD);
        ln_kernel<true><<<NN, 128>>>(pt, ln1g + l * DD, ln1b + l * DD, px, 1e-5f);

        hmma_gemm<0,0,true ><<<gFfn1, 256, SMEM_DYN>>>(px, w1s + ws_w1, b1 + l * DFF, pf, NN, DFF, DD);
        hmma_gemm<0,0,false><<<gProj, 256, SMEM_DYN>>>(pf, w2s + ws_w2, b2 + l * DD, pt, NN, DD, DFF);
        ln_kernel<true><<<NN, 128>>>(pt, ln2g + l * DD, ln2b + l * DD, px, 1e-5f);
    }

    ln_kernel<false><<<NN, 128>>>(px, lnfg, lnfb, out, 1e-6f);
}

// round 8
// speedup vs baseline: 2.1126x; 1.0551x over previous
#include <cuda_runtime.h>
#include <cuda_bf16.h>
#include <math.h>
#include <stdint.h>

// Problem constants
#define LAY 6
#define HH  8
#define DD  512
#define DK  64
#define DFF 2048
#define BB  8
#define SS  1024
#define NN  (BB*SS)          // 8192 rows

// ---------------- scratch (device globals: allocation-free) ----------------
__device__ float g_x[NN*DD];          // fp32 residual stream
__device__ float g_t[NN*DD];          // fp32 pre-LN buffer
// pre-split bf16 activations: hi at [0], lo at +count
__device__ __nv_bfloat16 g_xs[2*NN*DD];
__device__ __nv_bfloat16 g_qs[2*NN*DD];
__device__ __nv_bfloat16 g_ks[2*NN*DD];
__device__ __nv_bfloat16 g_vs[2*NN*DD];
__device__ __nv_bfloat16 g_os[2*NN*DD];
__device__ __nv_bfloat16 g_fs[2*NN*DFF];

// pre-split weights: per 128n x 64k tile: 8192 bf16 hi + 8192 bf16 lo,
// stored [n&127][k&63] row-major (B^T layout = mma "col" operand layout)
#define TILE_ELEMS 16384
__device__ __nv_bfloat16 g_wq_s[LAY*4*8*TILE_ELEMS];
__device__ __nv_bfloat16 g_wk_s[LAY*4*8*TILE_ELEMS];
__device__ __nv_bfloat16 g_wv_s[LAY*4*8*TILE_ELEMS];
__device__ __nv_bfloat16 g_wo_s[LAY*4*8*TILE_ELEMS];
__device__ __nv_bfloat16 g_w1_s[LAY*16*8*TILE_ELEMS];
__device__ __nv_bfloat16 g_w2_s[LAY*4*32*TILE_ELEMS];

// ---------------- PTX helpers ----------------
__device__ __forceinline__ uint32_t smem_u32(const void* p) {
    uint32_t a;
    asm("{ .reg .u64 t; cvta.to.shared.u64 t, %1; cvt.u32.u64 %0, t; }" : "=r"(a) : "l"(p));
    return a;
}
#define LDSM4(r, a) \
    asm volatile("ldmatrix.sync.aligned.m8n8.x4.shared.b16 {%0,%1,%2,%3}, [%4];" \
        : "=r"((r)[0]), "=r"((r)[1]), "=r"((r)[2]), "=r"((r)[3]) : "r"(a))
#define LDSM4T(r, a) \
    asm volatile("ldmatrix.sync.aligned.m8n8.x4.trans.shared.b16 {%0,%1,%2,%3}, [%4];" \
        : "=r"((r)[0]), "=r"((r)[1]), "=r"((r)[2]), "=r"((r)[3]) : "r"(a))
#define MMA_BF16(d, a, b0, b1) \
    asm volatile("mma.sync.aligned.m16n8k16.row.col.f32.bf16.bf16.f32 " \
        "{%0,%1,%2,%3}, {%4,%5,%6,%7}, {%8,%9}, {%0,%1,%2,%3};" \
        : "+f"((d)[0]), "+f"((d)[1]), "+f"((d)[2]), "+f"((d)[3]) \
        : "r"((a)[0]), "r"((a)[1]), "r"((a)[2]), "r"((a)[3]), "r"(b0), "r"(b1))
#define CP16(dst, src) \
    asm volatile("cp.async.cg.shared.global [%0], [%1], 16;" :: "r"(dst), "l"(src))
#define CP_COMMIT() asm volatile("cp.async.commit_group;" ::: "memory")
#define CP_WAIT1()  asm volatile("cp.async.wait_group 1;" ::: "memory")

// fast e^x on the FMA pipe (x <= 0 path; ~1.5e-7 rel error)
__device__ __forceinline__ float fexp(float x) {
    float t = x * 1.44269504f;
    t = fmaxf(t, -126.0f);
    float i = rintf(t);
    float f = t - i;
    float p =       1.54035304e-4f;
    p = fmaf(p, f, 1.33335581e-3f);
    p = fmaf(p, f, 9.61812910e-3f);
    p = fmaf(p, f, 5.55041086e-2f);
    p = fmaf(p, f, 2.40226507e-1f);
    p = fmaf(p, f, 6.93147182e-1f);
    p = fmaf(p, f, 1.0f);
    return p * __int_as_float(((int)i + 127) << 23);
}

__device__ __forceinline__ void split2(float a, float b, uint32_t& hi, uint32_t& lo) {
    __nv_bfloat162 h = __floats2bfloat162_rn(a, b);
    __nv_bfloat162 l = __floats2bfloat162_rn(a - __bfloat162float(h.x),
                                             b - __bfloat162float(h.y));
    hi = *(uint32_t*)&h;
    lo = *(uint32_t*)&l;
}

// ---------------- positional encoding (+ split write) ----------------
__global__ void add_pe_kernel(const float* __restrict__ src, float* __restrict__ x,
                              __nv_bfloat16* __restrict__ xh, __nv_bfloat16* __restrict__ xl) {
    int gid = blockIdx.x * 256 + threadIdx.x;       // one bf16x2 pair
    if (gid >= NN * DD / 2) return;
    int idx = gid * 2;
    int d = idx & (DD - 1);
    int s = (idx >> 9) & (SS - 1);
    int i = d >> 1;                                  // d even -> same i for both
    double div = exp((double)(2 * i) * (-9.210340371976184 / (double)DD));
    double ang = (double)s * div;
    float v0 = src[idx]     + (float)sin(ang);
    float v1 = src[idx + 1] + (float)cos(ang);
    x[idx] = v0; x[idx + 1] = v1;
    uint32_t hi, lo;
    split2(v0, v1, hi, lo);
    ((uint32_t*)xh)[gid] = hi;
    ((uint32_t*)xl)[gid] = lo;
}

// ---------------- weight pre-split (smem transpose, coalesced I/O) ----------------
__global__ __launch_bounds__(256)
void split_w_kernel(const float* __restrict__ W, __nv_bfloat16* __restrict__ out,
                    int K, int N, int blocked) {
    __shared__ float s[128][65];
    int tile = blockIdx.x;
    int kt = tile % (K >> 6);
    int rest = tile / (K >> 6);
    int nt = rest % (N >> 7);
    int l = rest / (N >> 7);
    int n0 = nt << 7, k0 = kt << 6;
    int t = threadIdx.x;
#pragma unroll
    for (int r = 0; r < 32; r++) {
        int i = r * 256 + t;
        int k = i >> 7, n = i & 127;
        float x;
        if (blocked) x = W[(((size_t)l * HH + ((n0 + n) >> 6)) * DD + k0 + k) * DK + ((n0 + n) & 63)];
        else         x = W[((size_t)l * K + k0 + k) * N + n0 + n];
        s[n][k] = x;
    }
    __syncthreads();
    uint32_t* oh = (uint32_t*)(out + (size_t)tile * TILE_ELEMS);
    uint32_t* ol = oh + 4096;
#pragma unroll
    for (int r = 0; r < 16; r++) {
        int i = r * 256 + t;
        int n = i >> 5, k = (i & 31) << 1;
        uint32_t hi, lo;
        split2(s[n][k], s[n][k + 1], hi, lo);
        oh[n * 32 + (k >> 1)] = hi;
        ol[n * 32 + (k >> 1)] = lo;
    }
}

// ---------------- HMMA GEMM (bf16x3, 128x128 tile, BK=32, 3-stage cp.async) ---
// stage (40960 B): A_hi 128x(64+16pad) @0, A_lo @10240, B_hi @20480, B_lo @30720
#define SA_LO 10240
#define SB_HI 20480
#define STG_SZ 40960
#define SMEM_DYN (3*STG_SZ)

// AMODE 0: A rowmajor [m][K].  AMODE 1: A bhsk gather.
// OMODE 0: fp32 rowmajor.  OMODE 1: split bhsk.  OMODE 2: split rowmajor.
template<int AMODE, int OMODE, bool RELU>
__global__ __launch_bounds__(256)
void hmma_gemm(const __nv_bfloat16* __restrict__ Ah, const __nv_bfloat16* __restrict__ Al,
               const __nv_bfloat16* __restrict__ Bt,
               const float* __restrict__ bias, float* __restrict__ Cf,
               __nv_bfloat16* __restrict__ Chi, __nv_bfloat16* __restrict__ Clo,
               int M, int N, int K, float scale) {
    extern __shared__ char smbuf[];
    uint32_t sb = smem_u32(smbuf);
    const int t = threadIdx.x, lane = t & 31, wid = t >> 5;
    const int wm = wid & 3, wn = wid >> 2;
    const int bm = blockIdx.y * 128, bn = blockIdx.x * 128;
    const int nk = K >> 5;
    const int ktile_n = K >> 6;

    float acc[2][8][4];
#pragma unroll
    for (int a = 0; a < 2; a++)
#pragma unroll
        for (int b = 0; b < 8; b++)
#pragma unroll
            for (int c = 0; c < 4; c++) acc[a][b][c] = 0.f;

    auto ISSUE = [&](int kt) {
        uint32_t stg = sb + (kt % 3) * STG_SZ;
        // A: 1024 16B chunks (hi/lo x 128 rows x 4)
#pragma unroll
        for (int r = 0; r < 4; r++) {
            int i = r * 256 + t;
            int comp = i >> 9, j = i & 511;
            int row = j >> 2, ch = j & 3;
            const char* base = (const char*)(comp ? Al : Ah);
            const char* src;
            if (AMODE == 0) {
                src = base + (((size_t)(bm + row) * K + kt * 32 + ch * 8) << 1);
            } else {
                int kk = kt * 32 + ch * 8;
                int mm = bm + row;
                src = base + (((size_t)(((mm >> 10) << 3) + (kk >> 6))) << 17)
                           + ((mm & 1023) << 7) + ((kk & 63) << 1);
            }
            CP16(stg + comp * 10240 + row * 80 + ch * 16, src);
        }
        // B: 1024 16B chunks from pre-swizzled tile
        const char* tb = (const char*)(Bt + ((size_t)blockIdx.x * ktile_n + (kt >> 1)) * TILE_ELEMS);
        int half = kt & 1;
#pragma unroll
        for (int r = 0; r < 4; r++) {
            int i = r * 256 + t;
            int comp = i >> 9, j = i & 511;
            int row = j >> 2, ch = j & 3;
            CP16(stg + SB_HI + comp * 10240 + row * 80 + ch * 16,
                 tb + comp * 16384 + row * 128 + half * 64 + ch * 16);
        }
    };

    auto COMPUTE = [&](int buf) {
        uint32_t stg = sb + buf * STG_SZ;
#pragma unroll
        for (int kk = 0; kk < 2; kk++) {
            int acol = (kk * 16 + (lane >> 4) * 8) * 2;
            uint32_t af[2][2][4];
#pragma unroll
            for (int mt = 0; mt < 2; mt++) {
                uint32_t aaddr = stg + (wm * 32 + mt * 16 + (lane & 15)) * 80 + acol;
                LDSM4(af[mt][0], aaddr);
                LDSM4(af[mt][1], aaddr + SA_LO);
            }
#pragma unroll
            for (int nt2 = 0; nt2 < 4; nt2++) {
                uint32_t baddr = stg + SB_HI + (wn * 64 + nt2 * 16 + (lane & 15)) * 80 + acol;
                uint32_t bh[4], bl[4];
                LDSM4(bh, baddr);
                LDSM4(bl, baddr + 10240);
#pragma unroll
                for (int mt = 0; mt < 2; mt++) {
                    MMA_BF16(acc[mt][nt2 * 2],     af[mt][0], bh[0], bh[2]);
                    MMA_BF16(acc[mt][nt2 * 2],     af[mt][0], bl[0], bl[2]);
                    MMA_BF16(acc[mt][nt2 * 2],     af[mt][1], bh[0], bh[2]);
                    MMA_BF16(acc[mt][nt2 * 2 + 1], af[mt][0], bh[1], bh[3]);
                    MMA_BF16(acc[mt][nt2 * 2 + 1], af[mt][0], bl[1], bl[3]);
                    MMA_BF16(acc[mt][nt2 * 2 + 1], af[mt][1], bh[1], bh[3]);
                }
            }
        }
    };

    ISSUE(0); CP_COMMIT();
    ISSUE(1); CP_COMMIT();
    for (int kt = 0; kt < nk; kt++) {
        CP_WAIT1();
        __syncthreads();
        if (kt + 2 < nk) ISSUE(kt + 2);
        CP_COMMIT();
        COMPUTE(kt % 3);
    }

    const int mrow = lane >> 2, ncol = (lane & 3) * 2;
#pragma unroll
    for (int mt = 0; mt < 2; mt++) {
#pragma unroll
        for (int nt = 0; nt < 8; nt++) {
            int c = bn + wn * 64 + nt * 8 + ncol;
            float2 bi = *(const float2*)(bias + c);
#pragma unroll
            for (int h = 0; h < 2; h++) {
                int m = bm + wm * 32 + mt * 16 + mrow + h * 8;
                float2 v;
                v.x = (acc[mt][nt][h * 2 + 0] + bi.x) * scale;
                v.y = (acc[mt][nt][h * 2 + 1] + bi.y) * scale;
                if (RELU) { v.x = fmaxf(v.x, 0.f); v.y = fmaxf(v.y, 0.f); }
                if (OMODE == 0) {
                    *(float2*)(Cf + (size_t)m * N + c) = v;
                } else if (OMODE == 1) {
                    size_t idx = (((size_t)(((m >> 10) << 3) + (c >> 6))) << 16)
                               + ((m & 1023) << 6) + (c & 63);
                    uint32_t hi, lo;
                    split2(v.x, v.y, hi, lo);
                    ((uint32_t*)Chi)[idx >> 1] = hi;
                    ((uint32_t*)Clo)[idx >> 1] = lo;
                } else {
                    size_t idx = (size_t)m * N + c;
                    uint32_t hi, lo;
                    split2(v.x, v.y, hi, lo);
                    ((uint32_t*)Chi)[idx >> 1] = hi;
                    ((uint32_t*)Clo)[idx >> 1] = lo;
                }
            }
        }
    }
}

// ---------------- HMMA flash attention (pre-split inputs, cp.async KV) -------
// grid (B*H, S/128), 256 threads. kv chunk = 64, 3-stage pipeline.
// smem: Q hi/lo 128x(128+16pad); per KV stage: Khi,Klo,Vhi,Vlo 64x144.
#define AQ_LO  18432
#define KVB    36864
#define KV_STG 36864
#define KV_KL  9216
#define KV_VH  18432
#define ATT_SMEM (36864 + 3*36864)

__global__ __launch_bounds__(256)
void attn_hmma(const __nv_bfloat16* __restrict__ Qh, const __nv_bfloat16* __restrict__ Ql,
               const __nv_bfloat16* __restrict__ Kh, const __nv_bfloat16* __restrict__ Kl,
               const __nv_bfloat16* __restrict__ Vh, const __nv_bfloat16* __restrict__ Vl,
               __nv_bfloat16* __restrict__ Oh, __nv_bfloat16* __restrict__ Ol) {
    extern __shared__ char smbuf[];
    uint32_t sb = smem_u32(smbuf);
    const int t = threadIdx.x, lane = t & 31, w = t >> 5;
    const int bh = blockIdx.x;
    const int qbase = blockIdx.y * 128;

    auto ISSUEKV = [&](int c) {
        uint32_t stg = sb + KVB + (c % 3) * KV_STG;
        int kc = c * 64;
#pragma unroll
        for (int r = 0; r < 8; r++) {
            int i = r * 256 + t;
            int ts = i >> 10;            // 0=K, 1=V
            int j = i & 1023;
            int comp = j >> 9;           // hi/lo
            int jj = j & 511;
            int row = jj >> 3, ch = jj & 7;
            const char* base = ts ? (const char*)(comp ? Vl : Vh)
                                  : (const char*)(comp ? Kl : Kh);
            const char* src = base + (((size_t)(bh * SS + kc + row) * DK + ch * 8) << 1);
            CP16(stg + ts * 18432 + comp * 9216 + row * 144 + ch * 16, src);
        }
    };

    ISSUEKV(0); CP_COMMIT();
    ISSUEKV(1); CP_COMMIT();

    // ---- stage Q (hi/lo) into smem: plain vector copy ----
#pragma unroll
    for (int r = 0; r < 8; r++) {
        int i = r * 256 + t;
        int comp = i >> 10;
        int j = i & 1023;
        int row = j >> 3, ch = j & 7;
        const char* src = (comp ? (const char*)Ql : (const char*)Qh)
                        + (((size_t)(bh * SS + qbase + row) * DK + ch * 8) << 1);
        *(uint4*)(smbuf + comp * AQ_LO + row * 144 + ch * 16) = *(const uint4*)src;
    }
    __syncthreads();

    uint32_t qh[4][4], ql[4][4];
#pragma unroll
    for (int kb = 0; kb < 4; kb++) {
        uint32_t addr = sb + (w * 16 + (lane & 15)) * 144 + (kb * 16 + (lane >> 4) * 8) * 2;
        LDSM4(qh[kb], addr);
        LDSM4(ql[kb], addr + AQ_LO);
    }

    float o[8][4];
#pragma unroll
    for (int i = 0; i < 8; i++)
#pragma unroll
        for (int j = 0; j < 4; j++) o[i][j] = 0.f;
    float m0 = -1.0e30f, m1 = -1.0e30f, l0 = 0.f, l1 = 0.f;

    for (int c = 0; c < SS / 64; c++) {
        CP_WAIT1();
        __syncthreads();
        if (c + 2 < SS / 64) ISSUEKV(c + 2);
        CP_COMMIT();
        uint32_t stg = sb + KVB + (c % 3) * KV_STG;

        // ---- S = Q K^T (3-term split) ----
        float s[8][4];
#pragma unroll
        for (int i = 0; i < 8; i++)
#pragma unroll
            for (int j = 0; j < 4; j++) s[i][j] = 0.f;
#pragma unroll
        for (int kvb = 0; kvb < 4; kvb++) {
#pragma unroll
            for (int kb = 0; kb < 4; kb++) {
                uint32_t addr = stg + (kvb * 16 + (lane & 15)) * 144 + (kb * 16 + (lane >> 4) * 8) * 2;
                uint32_t kfh[4], kfl[4];
                LDSM4(kfh, addr);
                LDSM4(kfl, addr + KV_KL);
                MMA_BF16(s[kvb * 2],     qh[kb], kfh[0], kfh[2]);
                MMA_BF16(s[kvb * 2],     qh[kb], kfl[0], kfl[2]);
                MMA_BF16(s[kvb * 2],     ql[kb], kfh[0], kfh[2]);
                MMA_BF16(s[kvb * 2 + 1], qh[kb], kfh[1], kfh[3]);
                MMA_BF16(s[kvb * 2 + 1], qh[kb], kfl[1], kfl[3]);
                MMA_BF16(s[kvb * 2 + 1], ql[kb], kfh[1], kfh[3]);
            }
        }

        // ---- online softmax ----
        float cm0 = -1.0e30f, cm1 = -1.0e30f;
#pragma unroll
        for (int nb = 0; nb < 8; nb++) {
            cm0 = fmaxf(cm0, fmaxf(s[nb][0], s[nb][1]));
            cm1 = fmaxf(cm1, fmaxf(s[nb][2], s[nb][3]));
        }
        cm0 = fmaxf(cm0, __shfl_xor_sync(0xffffffffu, cm0, 1));
        cm0 = fmaxf(cm0, __shfl_xor_sync(0xffffffffu, cm0, 2));
        cm1 = fmaxf(cm1, __shfl_xor_sync(0xffffffffu, cm1, 1));
        cm1 = fmaxf(cm1, __shfl_xor_sync(0xffffffffu, cm1, 2));
        float m0n = fmaxf(m0, cm0), m1n = fmaxf(m1, cm1);
        float c0 = fexp(m0 - m0n), c1 = fexp(m1 - m1n);
#pragma unroll
        for (int nb = 0; nb < 8; nb++) {
            o[nb][0] *= c0; o[nb][1] *= c0;
            o[nb][2] *= c1; o[nb][3] *= c1;
        }
        float ls0 = 0.f, ls1 = 0.f;
#pragma unroll
        for (int nb = 0; nb < 8; nb++) {
            s[nb][0] = fexp(s[nb][0] - m0n);
            s[nb][1] = fexp(s[nb][1] - m0n);
            s[nb][2] = fexp(s[nb][2] - m1n);
            s[nb][3] = fexp(s[nb][3] - m1n);
            ls0 += s[nb][0] + s[nb][1];
            ls1 += s[nb][2] + s[nb][3];
        }
        ls0 += __shfl_xor_sync(0xffffffffu, ls0, 1);
        ls0 += __shfl_xor_sync(0xffffffffu, ls0, 2);
        ls1 += __shfl_xor_sync(0xffffffffu, ls1, 1);
        ls1 += __shfl_xor_sync(0xffffffffu, ls1, 2);
        l0 = l0 * c0 + ls0;
        l1 = l1 * c1 + ls1;
        m0 = m0n; m1 = m1n;

        // ---- O += P V (3-term split) ----
#pragma unroll
        for (int kb = 0; kb < 4; kb++) {
            uint32_t ph[4], pl[4];
            split2(s[2 * kb][0],     s[2 * kb][1],     ph[0], pl[0]);
            split2(s[2 * kb][2],     s[2 * kb][3],     ph[1], pl[1]);
            split2(s[2 * kb + 1][0], s[2 * kb + 1][1], ph[2], pl[2]);
            split2(s[2 * kb + 1][2], s[2 * kb + 1][3], ph[3], pl[3]);
#pragma unroll
            for (int db = 0; db < 4; db++) {
                uint32_t addr = stg + KV_VH + (kb * 16 + (lane & 15)) * 144 + (db * 16 + (lane >> 4) * 8) * 2;
                uint32_t vfh[4], vfl[4];
                LDSM4T(vfh, addr);
                LDSM4T(vfl, addr + KV_KL);
                MMA_BF16(o[db * 2],     ph, vfh[0], vfh[1]);
                MMA_BF16(o[db * 2],     ph, vfl[0], vfl[1]);
                MMA_BF16(o[db * 2],     pl, vfh[0], vfh[1]);
                MMA_BF16(o[db * 2 + 1], ph, vfh[2], vfh[3]);
                MMA_BF16(o[db * 2 + 1], ph, vfl[2], vfl[3]);
                MMA_BF16(o[db * 2 + 1], pl, vfh[2], vfh[3]);
            }
        }
    }

    // ---- normalize and write split-bf16 ----
    float inv0 = 1.f / l0, inv1 = 1.f / l1;
    int r0 = qbase + w * 16 + (lane >> 2);
    int c0c = (lane & 3) * 2;
#pragma unroll
    for (int db = 0; db < 8; db++) {
        int c = db * 8 + c0c;
        uint32_t hi, lo;
        size_t idx0 = ((size_t)bh * SS + r0) * DK + c;
        split2(o[db][0] * inv0, o[db][1] * inv0, hi, lo);
        ((uint32_t*)Oh)[idx0 >> 1] = hi;
        ((uint32_t*)Ol)[idx0 >> 1] = lo;
        size_t idx1 = ((size_t)bh * SS + r0 + 8) * DK + c;
        split2(o[db][2] * inv1, o[db][3] * inv1, hi, lo);
        ((uint32_t*)Oh)[idx1 >> 1] = hi;
        ((uint32_t*)Ol)[idx1 >> 1] = lo;
    }
}

// ---------------- LayerNorm (+ optional residual add, + optional split out) --
template<bool ADD, bool SPLIT>
__global__ __launch_bounds__(128)
void ln_kernel(const float* __restrict__ src, const float* __restrict__ gamma,
               const float* __restrict__ beta, float* __restrict__ xio,
               __nv_bfloat16* __restrict__ xh, __nv_bfloat16* __restrict__ xl, float eps) {
    int row = blockIdx.x;
    int t = threadIdx.x;
    int lane = t & 31, wid = t >> 5;
    const float4* sp = (const float4*)(src + (size_t)row * DD);
    float4 v = sp[t];

    __shared__ float red[4];
    __shared__ float bsum, bvar;

    float s = (v.x + v.y) + (v.z + v.w);
#pragma unroll
    for (int o = 16; o > 0; o >>= 1) s += __shfl_xor_sync(0xffffffffu, s, o);
    if (lane == 0) red[wid] = s;
    __syncthreads();
    if (t == 0) bsum = (red[0] + red[1]) + (red[2] + red[3]);
    __syncthreads();
    float mu = bsum * (1.f / DD);

    float dx = v.x - mu, dy = v.y - mu, dz = v.z - mu, dw = v.w - mu;
    float s2 = (dx * dx + dy * dy) + (dz * dz + dw * dw);
#pragma unroll
    for (int o = 16; o > 0; o >>= 1) s2 += __shfl_xor_sync(0xffffffffu, s2, o);
    if (lane == 0) red[wid] = s2;
    __syncthreads();
    if (t == 0) bvar = (red[0] + red[1]) + (red[2] + red[3]);
    __syncthreads();
    float rstd = rsqrtf(bvar * (1.f / DD) + eps);

    int c = t * 4;
    float4 g = *(const float4*)(gamma + c);
    float4 b = *(const float4*)(beta + c);
    float4 o4;
    o4.x = dx * rstd * g.x + b.x;
    o4.y = dy * rstd * g.y + b.y;
    o4.z = dz * rstd * g.z + b.z;
    o4.w = dw * rstd * g.w + b.w;
    float4* xp = (float4*)(xio + (size_t)row * DD);
    if (ADD) {
        float4 xo = xp[t];
        o4.x += xo.x; o4.y += xo.y; o4.z += xo.z; o4.w += xo.w;
    }
    xp[t] = o4;
    if (SPLIT) {
        size_t pidx = ((size_t)row * DD + c) >> 1;
        uint32_t hi, lo;
        split2(o4.x, o4.y, hi, lo);
        ((uint32_t*)xh)[pidx] = hi; ((uint32_t*)xl)[pidx] = lo;
        split2(o4.z, o4.w, hi, lo);
        ((uint32_t*)xh)[pidx + 1] = hi; ((uint32_t*)xl)[pidx + 1] = lo;
    }
}

// ---------------- driver ----------------
extern "C" void kernel_launch(void* const* d_in, const int* in_sizes, int n_in,
                              void* d_out, int out_size) {
    const float* src  = (const float*)d_in[0];
    const float* Wq   = (const float*)d_in[1];
    const float* bq   = (const float*)d_in[2];
    const float* Wk   = (const float*)d_in[3];
    const float* bk   = (const float*)d_in[4];
    const float* Wv   = (const float*)d_in[5];
    const float* bv   = (const float*)d_in[6];
    const float* Wo   = (const float*)d_in[7];
    const float* bo   = (const float*)d_in[8];
    const float* ln1g = (const float*)d_in[9];
    const float* ln1b = (const float*)d_in[10];
    const float* W1   = (const float*)d_in[11];
    const float* b1   = (const float*)d_in[12];
    const float* W2   = (const float*)d_in[13];
    const float* b2   = (const float*)d_in[14];
    const float* ln2g = (const float*)d_in[15];
    const float* ln2b = (const float*)d_in[16];
    const float* lnfg = (const float*)d_in[17];
    const float* lnfb = (const float*)d_in[18];
    float* out = (float*)d_out;

    float *px, *pt;
    __nv_bfloat16 *xs, *qs, *ks, *vs, *os, *fs;
    __nv_bfloat16 *wqs, *wks, *wvs, *wos, *w1s, *w2s;
    cudaGetSymbolAddress((void**)&px, g_x);
    cudaGetSymbolAddress((void**)&pt, g_t);
    cudaGetSymbolAddress((void**)&xs, g_xs);
    cudaGetSymbolAddress((void**)&qs, g_qs);
    cudaGetSymbolAddress((void**)&ks, g_ks);
    cudaGetSymbolAddress((void**)&vs, g_vs);
    cudaGetSymbolAddress((void**)&os, g_os);
    cudaGetSymbolAddress((void**)&fs, g_fs);
    cudaGetSymbolAddress((void**)&wqs, g_wq_s);
    cudaGetSymbolAddress((void**)&wks, g_wk_s);
    cudaGetSymbolAddress((void**)&wvs, g_wv_s);
    cudaGetSymbolAddress((void**)&wos, g_wo_s);
    cudaGetSymbolAddress((void**)&w1s, g_w1_s);
    cudaGetSymbolAddress((void**)&w2s, g_w2_s);

    __nv_bfloat16 *xh = xs, *xl = xs + (size_t)NN * DD;
    __nv_bfloat16 *qh = qs, *ql = qs + (size_t)NN * DD;
    __nv_bfloat16 *kh = ks, *kl = ks + (size_t)NN * DD;
    __nv_bfloat16 *vh = vs, *vl = vs + (size_t)NN * DD;
    __nv_bfloat16 *oh = os, *ol = os + (size_t)NN * DD;
    __nv_bfloat16 *fh = fs, *fl = fs + (size_t)NN * DFF;

    cudaFuncSetAttribute(hmma_gemm<0,1,false>, cudaFuncAttributeMaxDynamicSharedMemorySize, SMEM_DYN);
    cudaFuncSetAttribute(hmma_gemm<1,0,false>, cudaFuncAttributeMaxDynamicSharedMemorySize, SMEM_DYN);
    cudaFuncSetAttribute(hmma_gemm<0,2,true >, cudaFuncAttributeMaxDynamicSharedMemorySize, SMEM_DYN);
    cudaFuncSetAttribute(hmma_gemm<0,0,false>, cudaFuncAttributeMaxDynamicSharedMemorySize, SMEM_DYN);
    cudaFuncSetAttribute(attn_hmma, cudaFuncAttributeMaxDynamicSharedMemorySize, ATT_SMEM);

    // weight pre-split (tile-transpose, coalesced)
    split_w_kernel<<<LAY * 4 * 8, 256>>>(Wq, wqs, DD, DD, 1);
    split_w_kernel<<<LAY * 4 * 8, 256>>>(Wk, wks, DD, DD, 1);
    split_w_kernel<<<LAY * 4 * 8, 256>>>(Wv, wvs, DD, DD, 1);
    split_w_kernel<<<LAY * 4 * 8, 256>>>(Wo, wos, DD, DD, 0);
    split_w_kernel<<<LAY * 16 * 8, 256>>>(W1, w1s, DD, DFF, 0);
    split_w_kernel<<<LAY * 4 * 32, 256>>>(W2, w2s, DFF, DD, 0);

    add_pe_kernel<<<(NN * DD / 2 + 255) / 256, 256>>>(src, px, xh, xl);

    dim3 gProj(4, 64);    // N=512
    dim3 gFfn1(16, 64);   // N=2048
    dim3 gAttn(BB * HH, SS / 128);

    for (int l = 0; l < LAY; l++) {
        size_t ws_proj = (size_t)l * 4 * 8 * TILE_ELEMS;
        size_t ws_w1   = (size_t)l * 16 * 8 * TILE_ELEMS;
        size_t ws_w2   = (size_t)l * 4 * 32 * TILE_ELEMS;

        // QKV: split rowmajor A -> split bhsk out (Q pre-scaled by 1/sqrt(dk))
        hmma_gemm<0,1,false><<<gProj, 256, SMEM_DYN>>>(xh, xl, wqs + ws_proj, bq + l * HH * DK,
                                                       nullptr, qh, ql, NN, DD, DD, 0.125f);
        hmma_gemm<0,1,false><<<gProj, 256, SMEM_DYN>>>(xh, xl, wks + ws_proj, bk + l * HH * DK,
                                                       nullptr, kh, kl, NN, DD, DD, 1.0f);
        hmma_gemm<0,1,false><<<gProj, 256, SMEM_DYN>>>(xh, xl, wvs + ws_proj, bv + l * HH * DK,
                                                       nullptr, vh, vl, NN, DD, DD, 1.0f);

        attn_hmma<<<gAttn, 256, ATT_SMEM>>>(qh, ql, kh, kl, vh, vl, oh, ol);

        // O-proj: bhsk-gather split A -> fp32 rowmajor
        hmma_gemm<1,0,false><<<gProj, 256, SMEM_DYN>>>(oh, ol, wos + ws_proj, bo + l * DD,
                                                       pt, nullptr, nullptr, NN, DD, DD, 1.0f);
        ln_kernel<true,true><<<NN, 128>>>(pt, ln1g + l * DD, ln1b + l * DD, px, xh, xl, 1e-5f);

        // FFN
        hmma_gemm<0,2,true ><<<gFfn1, 256, SMEM_DYN>>>(xh, xl, w1s + ws_w1, b1 + l * DFF,
                                                       nullptr, fh, fl, NN, DFF, DD, 1.0f);
        hmma_gemm<0,0,false><<<gProj, 256, SMEM_DYN>>>(fh, fl, w2s + ws_w2, b2 + l * DD,
                                                       pt, nullptr, nullptr, NN, DD, DFF, 1.0f);
        ln_kernel<true,true><<<NN, 128>>>(pt, ln2g + l * DD, ln2b + l * DD, px, xh, xl, 1e-5f);
    }

    ln_kernel<false,false><<<NN, 128>>>(px, lnfg, lnfb, out, nullptr, nullptr, 1e-6f);
}

// round 9
// speedup vs baseline: 2.1762x; 1.0301x over previous
#include <cuda_runtime.h>
#include <cuda_bf16.h>
#include <math.h>
#include <stdint.h>

// Problem constants
#define LAY 6
#define HH  8
#define DD  512
#define DK  64
#define DFF 2048
#define BB  8
#define SS  1024
#define NN  (BB*SS)          // 8192 rows

// ---------------- scratch (device globals: allocation-free) ----------------
__device__ float g_x[NN*DD];          // fp32 residual stream
__device__ float g_t[NN*DD];          // fp32 pre-LN buffer
__device__ __nv_bfloat16 g_xs[2*NN*DD];
__device__ __nv_bfloat16 g_qs[2*NN*DD];
__device__ __nv_bfloat16 g_ks[2*NN*DD];
__device__ __nv_bfloat16 g_vs[2*NN*DD];
__device__ __nv_bfloat16 g_os[2*NN*DD];
__device__ __nv_bfloat16 g_fs[2*NN*DFF];

// pre-split weights: per 128n x 64k tile: 8192 bf16 hi + 8192 bf16 lo
#define TILE_ELEMS 16384
__device__ __nv_bfloat16 g_wq_s[LAY*4*8*TILE_ELEMS];
__device__ __nv_bfloat16 g_wk_s[LAY*4*8*TILE_ELEMS];
__device__ __nv_bfloat16 g_wv_s[LAY*4*8*TILE_ELEMS];
__device__ __nv_bfloat16 g_wo_s[LAY*4*8*TILE_ELEMS];
__device__ __nv_bfloat16 g_w1_s[LAY*16*8*TILE_ELEMS];
__device__ __nv_bfloat16 g_w2_s[LAY*4*32*TILE_ELEMS];

// ---------------- PTX helpers ----------------
__device__ __forceinline__ uint32_t smem_u32(const void* p) {
    uint32_t a;
    asm("{ .reg .u64 t; cvta.to.shared.u64 t, %1; cvt.u32.u64 %0, t; }" : "=r"(a) : "l"(p));
    return a;
}
#define LDSM4(r, a) \
    asm volatile("ldmatrix.sync.aligned.m8n8.x4.shared.b16 {%0,%1,%2,%3}, [%4];" \
        : "=r"((r)[0]), "=r"((r)[1]), "=r"((r)[2]), "=r"((r)[3]) : "r"(a))
#define LDSM4T(r, a) \
    asm volatile("ldmatrix.sync.aligned.m8n8.x4.trans.shared.b16 {%0,%1,%2,%3}, [%4];" \
        : "=r"((r)[0]), "=r"((r)[1]), "=r"((r)[2]), "=r"((r)[3]) : "r"(a))
#define MMA_BF16(d, a, b0, b1) \
    asm volatile("mma.sync.aligned.m16n8k16.row.col.f32.bf16.bf16.f32 " \
        "{%0,%1,%2,%3}, {%4,%5,%6,%7}, {%8,%9}, {%0,%1,%2,%3};" \
        : "+f"((d)[0]), "+f"((d)[1]), "+f"((d)[2]), "+f"((d)[3]) \
        : "r"((a)[0]), "r"((a)[1]), "r"((a)[2]), "r"((a)[3]), "r"(b0), "r"(b1))
#define CP16(dst, src) \
    asm volatile("cp.async.cg.shared.global [%0], [%1], 16;" :: "r"(dst), "l"(src))
#define CP_COMMIT() asm volatile("cp.async.commit_group;" ::: "memory")
#define CP_WAIT1()  asm volatile("cp.async.wait_group 1;" ::: "memory")

// fast e^x on the FMA pipe (x <= 0 path)
__device__ __forceinline__ float fexp(float x) {
    float t = x * 1.44269504f;
    t = fmaxf(t, -126.0f);
    float i = rintf(t);
    float f = t - i;
    float p =       1.54035304e-4f;
    p = fmaf(p, f, 1.33335581e-3f);
    p = fmaf(p, f, 9.61812910e-3f);
    p = fmaf(p, f, 5.55041086e-2f);
    p = fmaf(p, f, 2.40226507e-1f);
    p = fmaf(p, f, 6.93147182e-1f);
    p = fmaf(p, f, 1.0f);
    return p * __int_as_float(((int)i + 127) << 23);
}

__device__ __forceinline__ void split2(float a, float b, uint32_t& hi, uint32_t& lo) {
    __nv_bfloat162 h = __floats2bfloat162_rn(a, b);
    __nv_bfloat162 l = __floats2bfloat162_rn(a - __bfloat162float(h.x),
                                             b - __bfloat162float(h.y));
    hi = *(uint32_t*)&h;
    lo = *(uint32_t*)&l;
}

// ---------------- weight pre-split: ALL weights in one launch ----------------
__device__ __forceinline__ void split_tile(const float* __restrict__ W,
                                           __nv_bfloat16* __restrict__ out,
                                           int K, int N, int blocked, int tile,
                                           float (*s)[65]) {
    int kt = tile % (K >> 6);
    int rest = tile / (K >> 6);
    int nt = rest % (N >> 7);
    int l = rest / (N >> 7);
    int n0 = nt << 7, k0 = kt << 6;
    int t = threadIdx.x;
#pragma unroll
    for (int r = 0; r < 32; r++) {
        int i = r * 256 + t;
        int k = i >> 7, n = i & 127;
        float x;
        if (blocked) x = W[(((size_t)l * HH + ((n0 + n) >> 6)) * DD + k0 + k) * DK + ((n0 + n) & 63)];
        else         x = W[((size_t)l * K + k0 + k) * N + n0 + n];
        s[n][k] = x;
    }
    __syncthreads();
    uint32_t* oh = (uint32_t*)(out + (size_t)tile * TILE_ELEMS);
    uint32_t* ol = oh + 4096;
#pragma unroll
    for (int r = 0; r < 16; r++) {
        int i = r * 256 + t;
        int n = i >> 5, k = (i & 31) << 1;
        uint32_t hi, lo;
        split2(s[n][k], s[n][k + 1], hi, lo);
        oh[n * 32 + (k >> 1)] = hi;
        ol[n * 32 + (k >> 1)] = lo;
    }
}

__global__ __launch_bounds__(256)
void split_all_kernel(const float* Wq, const float* Wk, const float* Wv,
                      const float* Wo, const float* W1, const float* W2,
                      __nv_bfloat16* oq, __nv_bfloat16* ok, __nv_bfloat16* ov,
                      __nv_bfloat16* oo, __nv_bfloat16* o1, __nv_bfloat16* o2) {
    __shared__ float s[128][65];
    int b = blockIdx.x;
    if      (b < 192)  split_tile(Wq, oq, DD,  DD,  1, b,        s);
    else if (b < 384)  split_tile(Wk, ok, DD,  DD,  1, b - 192,  s);
    else if (b < 576)  split_tile(Wv, ov, DD,  DD,  1, b - 384,  s);
    else if (b < 768)  split_tile(Wo, oo, DD,  DD,  0, b - 576,  s);
    else if (b < 1536) split_tile(W1, o1, DD,  DFF, 0, b - 768,  s);
    else               split_tile(W2, o2, DFF, DD,  0, b - 1536, s);
}

// ---------------- positional encoding (+ split write) ----------------
__global__ void add_pe_kernel(const float* __restrict__ src, float* __restrict__ x,
                              __nv_bfloat16* __restrict__ xh, __nv_bfloat16* __restrict__ xl) {
    int gid = blockIdx.x * 256 + threadIdx.x;
    if (gid >= NN * DD / 2) return;
    int idx = gid * 2;
    int d = idx & (DD - 1);
    int s = (idx >> 9) & (SS - 1);
    int i = d >> 1;
    double div = exp((double)(2 * i) * (-9.210340371976184 / (double)DD));
    double ang = (double)s * div;
    float v0 = src[idx]     + (float)sin(ang);
    float v1 = src[idx + 1] + (float)cos(ang);
    x[idx] = v0; x[idx + 1] = v1;
    uint32_t hi, lo;
    split2(v0, v1, hi, lo);
    ((uint32_t*)xh)[gid] = hi;
    ((uint32_t*)xl)[gid] = lo;
}

// ------- HMMA GEMM (bf16x3, 256x128 CTA tile, 64x64 warp tile, 3-stage) ------
// stage (61440 B): A_hi 256x(64+16pad)B @0, A_lo @20480, B_hi @40960, B_lo @51200
#define GS_ALO 20480
#define GS_BHI 40960
#define GS_BLO 10240     /* offset from GS_BHI */
#define GS_STG 61440
#define SMEM_DYN (3*GS_STG)

// AMODE 0: A rowmajor.  AMODE 1: A bhsk gather.
// OMODE 0: fp32 rowmajor.  OMODE 1: split bhsk.  OMODE 2: split rowmajor.
template<int AMODE, int OMODE, bool RELU>
__global__ __launch_bounds__(256, 1)
void hmma_gemm(const __nv_bfloat16* __restrict__ Ah, const __nv_bfloat16* __restrict__ Al,
               const __nv_bfloat16* __restrict__ Bt,
               const float* __restrict__ bias, float* __restrict__ Cf,
               __nv_bfloat16* __restrict__ Chi, __nv_bfloat16* __restrict__ Clo,
               int M, int N, int K, float scale) {
    extern __shared__ char smbuf[];
    uint32_t sb = smem_u32(smbuf);
    const int t = threadIdx.x, lane = t & 31, wid = t >> 5;
    const int wm = wid & 3, wn = wid >> 2;
    const int bm = blockIdx.y * 256, bn = blockIdx.x * 128;
    const int nk = K >> 5;
    const int ktile_n = K >> 6;

    float acc[4][8][4];
#pragma unroll
    for (int a = 0; a < 4; a++)
#pragma unroll
        for (int b = 0; b < 8; b++)
#pragma unroll
            for (int c = 0; c < 4; c++) acc[a][b][c] = 0.f;

    auto ISSUE = [&](int kt) {
        uint32_t stg = sb + (kt % 3) * GS_STG;
        // A: 2048 16B chunks (hi/lo x 256 rows x 4)
#pragma unroll
        for (int r = 0; r < 8; r++) {
            int i = r * 256 + t;
            int comp = i >> 10, j = i & 1023;
            int row = j >> 2, ch = j & 3;
            const char* base = (const char*)(comp ? Al : Ah);
            const char* src;
            if (AMODE == 0) {
                src = base + (((size_t)(bm + row) * K + kt * 32 + ch * 8) << 1);
            } else {
                int kk = kt * 32 + ch * 8;
                int mm = bm + row;
                src = base + (((size_t)(((mm >> 10) << 3) + (kk >> 6))) << 17)
                           + ((mm & 1023) << 7) + ((kk & 63) << 1);
            }
            CP16(stg + comp * GS_ALO + row * 80 + ch * 16, src);
        }
        // B: 1024 16B chunks from pre-swizzled tile
        const char* tb = (const char*)(Bt + ((size_t)blockIdx.x * ktile_n + (kt >> 1)) * TILE_ELEMS);
        int half = kt & 1;
#pragma unroll
        for (int r = 0; r < 4; r++) {
            int i = r * 256 + t;
            int comp = i >> 9, j = i & 511;
            int row = j >> 2, ch = j & 3;
            CP16(stg + GS_BHI + comp * GS_BLO + row * 80 + ch * 16,
                 tb + comp * 16384 + row * 128 + half * 64 + ch * 16);
        }
    };

    auto COMPUTE = [&](int buf) {
        uint32_t stg = sb + buf * GS_STG;
#pragma unroll
        for (int kk = 0; kk < 2; kk++) {
            int acol = (kk * 16 + (lane >> 4) * 8) * 2;
            uint32_t af[4][2][4];
#pragma unroll
            for (int mt = 0; mt < 4; mt++) {
                uint32_t aaddr = stg + (wm * 64 + mt * 16 + (lane & 15)) * 80 + acol;
                LDSM4(af[mt][0], aaddr);
                LDSM4(af[mt][1], aaddr + GS_ALO);
            }
#pragma unroll
            for (int nt2 = 0; nt2 < 4; nt2++) {
                uint32_t baddr = stg + GS_BHI + (wn * 64 + nt2 * 16 + (lane & 15)) * 80 + acol;
                uint32_t bh[4], bl[4];
                LDSM4(bh, baddr);
                LDSM4(bl, baddr + GS_BLO);
#pragma unroll
                for (int mt = 0; mt < 4; mt++) {
                    MMA_BF16(acc[mt][nt2 * 2],     af[mt][0], bh[0], bh[2]);
                    MMA_BF16(acc[mt][nt2 * 2],     af[mt][0], bl[0], bl[2]);
                    MMA_BF16(acc[mt][nt2 * 2],     af[mt][1], bh[0], bh[2]);
                    MMA_BF16(acc[mt][nt2 * 2 + 1], af[mt][0], bh[1], bh[3]);
                    MMA_BF16(acc[mt][nt2 * 2 + 1], af[mt][0], bl[1], bl[3]);
                    MMA_BF16(acc[mt][nt2 * 2 + 1], af[mt][1], bh[1], bh[3]);
                }
            }
        }
    };

    ISSUE(0); CP_COMMIT();
    ISSUE(1); CP_COMMIT();
    for (int kt = 0; kt < nk; kt++) {
        CP_WAIT1();
        __syncthreads();
        if (kt + 2 < nk) ISSUE(kt + 2);
        CP_COMMIT();
        COMPUTE(kt % 3);
    }

    const int mrow = lane >> 2, ncol = (lane & 3) * 2;
#pragma unroll
    for (int mt = 0; mt < 4; mt++) {
#pragma unroll
        for (int nt = 0; nt < 8; nt++) {
            int c = bn + wn * 64 + nt * 8 + ncol;
            float2 bi = *(const float2*)(bias + c);
#pragma unroll
            for (int h = 0; h < 2; h++) {
                int m = bm + wm * 64 + mt * 16 + mrow + h * 8;
                float2 v;
                v.x = (acc[mt][nt][h * 2 + 0] + bi.x) * scale;
                v.y = (acc[mt][nt][h * 2 + 1] + bi.y) * scale;
                if (RELU) { v.x = fmaxf(v.x, 0.f); v.y = fmaxf(v.y, 0.f); }
                if (OMODE == 0) {
                    *(float2*)(Cf + (size_t)m * N + c) = v;
                } else if (OMODE == 1) {
                    size_t idx = (((size_t)(((m >> 10) << 3) + (c >> 6))) << 16)
                               + ((m & 1023) << 6) + (c & 63);
                    uint32_t hi, lo;
                    split2(v.x, v.y, hi, lo);
                    ((uint32_t*)Chi)[idx >> 1] = hi;
                    ((uint32_t*)Clo)[idx >> 1] = lo;
                } else {
                    size_t idx = (size_t)m * N + c;
                    uint32_t hi, lo;
                    split2(v.x, v.y, hi, lo);
                    ((uint32_t*)Chi)[idx >> 1] = hi;
                    ((uint32_t*)Clo)[idx >> 1] = lo;
                }
            }
        }
    }
}

// ---------------- HMMA flash attention (pre-split inputs, cp.async KV) -------
#define AQ_LO  18432
#define KVB    36864
#define KV_STG 36864
#define KV_KL  9216
#define KV_VH  18432
#define ATT_SMEM (36864 + 3*36864)

__global__ __launch_bounds__(256)
void attn_hmma(const __nv_bfloat16* __restrict__ Qh, const __nv_bfloat16* __restrict__ Ql,
               const __nv_bfloat16* __restrict__ Kh, const __nv_bfloat16* __restrict__ Kl,
               const __nv_bfloat16* __restrict__ Vh, const __nv_bfloat16* __restrict__ Vl,
               __nv_bfloat16* __restrict__ Oh, __nv_bfloat16* __restrict__ Ol) {
    extern __shared__ char smbuf[];
    uint32_t sb = smem_u32(smbuf);
    const int t = threadIdx.x, lane = t & 31, w = t >> 5;
    const int bh = blockIdx.x;
    const int qbase = blockIdx.y * 128;

    auto ISSUEKV = [&](int c) {
        uint32_t stg = sb + KVB + (c % 3) * KV_STG;
        int kc = c * 64;
#pragma unroll
        for (int r = 0; r < 8; r++) {
            int i = r * 256 + t;
            int ts = i >> 10;
            int j = i & 1023;
            int comp = j >> 9;
            int jj = j & 511;
            int row = jj >> 3, ch = jj & 7;
            const char* base = ts ? (const char*)(comp ? Vl : Vh)
                                  : (const char*)(comp ? Kl : Kh);
            const char* src = base + (((size_t)(bh * SS + kc + row) * DK + ch * 8) << 1);
            CP16(stg + ts * 18432 + comp * 9216 + row * 144 + ch * 16, src);
        }
    };

    ISSUEKV(0); CP_COMMIT();
    ISSUEKV(1); CP_COMMIT();

#pragma unroll
    for (int r = 0; r < 8; r++) {
        int i = r * 256 + t;
        int comp = i >> 10;
        int j = i & 1023;
        int row = j >> 3, ch = j & 7;
        const char* src = (comp ? (const char*)Ql : (const char*)Qh)
                        + (((size_t)(bh * SS + qbase + row) * DK + ch * 8) << 1);
        *(uint4*)(smbuf + comp * AQ_LO + row * 144 + ch * 16) = *(const uint4*)src;
    }
    __syncthreads();

    uint32_t qh[4][4], ql[4][4];
#pragma unroll
    for (int kb = 0; kb < 4; kb++) {
        uint32_t addr = sb + (w * 16 + (lane & 15)) * 144 + (kb * 16 + (lane >> 4) * 8) * 2;
        LDSM4(qh[kb], addr);
        LDSM4(ql[kb], addr + AQ_LO);
    }

    float o[8][4];
#pragma unroll
    for (int i = 0; i < 8; i++)
#pragma unroll
        for (int j = 0; j < 4; j++) o[i][j] = 0.f;
    float m0 = -1.0e30f, m1 = -1.0e30f, l0 = 0.f, l1 = 0.f;

    for (int c = 0; c < SS / 64; c++) {
        CP_WAIT1();
        __syncthreads();
        if (c + 2 < SS / 64) ISSUEKV(c + 2);
        CP_COMMIT();
        uint32_t stg = sb + KVB + (c % 3) * KV_STG;

        float s[8][4];
#pragma unroll
        for (int i = 0; i < 8; i++)
#pragma unroll
            for (int j = 0; j < 4; j++) s[i][j] = 0.f;
#pragma unroll
        for (int kvb = 0; kvb < 4; kvb++) {
#pragma unroll
            for (int kb = 0; kb < 4; kb++) {
                uint32_t addr = stg + (kvb * 16 + (lane & 15)) * 144 + (kb * 16 + (lane >> 4) * 8) * 2;
                uint32_t kfh[4], kfl[4];
                LDSM4(kfh, addr);
                LDSM4(kfl, addr + KV_KL);
                MMA_BF16(s[kvb * 2],     qh[kb], kfh[0], kfh[2]);
                MMA_BF16(s[kvb * 2],     qh[kb], kfl[0], kfl[2]);
                MMA_BF16(s[kvb * 2],     ql[kb], kfh[0], kfh[2]);
                MMA_BF16(s[kvb * 2 + 1], qh[kb], kfh[1], kfh[3]);
                MMA_BF16(s[kvb * 2 + 1], qh[kb], kfl[1], kfl[3]);
                MMA_BF16(s[kvb * 2 + 1], ql[kb], kfh[1], kfh[3]);
            }
        }

        float cm0 = -1.0e30f, cm1 = -1.0e30f;
#pragma unroll
        for (int nb = 0; nb < 8; nb++) {
            cm0 = fmaxf(cm0, fmaxf(s[nb][0], s[nb][1]));
            cm1 = fmaxf(cm1, fmaxf(s[nb][2], s[nb][3]));
        }
        cm0 = fmaxf(cm0, __shfl_xor_sync(0xffffffffu, cm0, 1));
        cm0 = fmaxf(cm0, __shfl_xor_sync(0xffffffffu, cm0, 2));
        cm1 = fmaxf(cm1, __shfl_xor_sync(0xffffffffu, cm1, 1));
        cm1 = fmaxf(cm1, __shfl_xor_sync(0xffffffffu, cm1, 2));
        float m0n = fmaxf(m0, cm0), m1n = fmaxf(m1, cm1);
        float c0 = fexp(m0 - m0n), c1 = fexp(m1 - m1n);
#pragma unroll
        for (int nb = 0; nb < 8; nb++) {
            o[nb][0] *= c0; o[nb][1] *= c0;
            o[nb][2] *= c1; o[nb][3] *= c1;
        }
        float ls0 = 0.f, ls1 = 0.f;
#pragma unroll
        for (int nb = 0; nb < 8; nb++) {
            s[nb][0] = fexp(s[nb][0] - m0n);
            s[nb][1] = fexp(s[nb][1] - m0n);
            s[nb][2] = fexp(s[nb][2] - m1n);
            s[nb][3] = fexp(s[nb][3] - m1n);
            ls0 += s[nb][0] + s[nb][1];
            ls1 += s[nb][2] + s[nb][3];
        }
        ls0 += __shfl_xor_sync(0xffffffffu, ls0, 1);
        ls0 += __shfl_xor_sync(0xffffffffu, ls0, 2);
        ls1 += __shfl_xor_sync(0xffffffffu, ls1, 1);
        ls1 += __shfl_xor_sync(0xffffffffu, ls1, 2);
        l0 = l0 * c0 + ls0;
        l1 = l1 * c1 + ls1;
        m0 = m0n; m1 = m1n;

#pragma unroll
        for (int kb = 0; kb < 4; kb++) {
            uint32_t ph[4], pl[4];
            split2(s[2 * kb][0],     s[2 * kb][1],     ph[0], pl[0]);
            split2(s[2 * kb][2],     s[2 * kb][3],     ph[1], pl[1]);
            split2(s[2 * kb + 1][0], s[2 * kb + 1][1], ph[2], pl[2]);
            split2(s[2 * kb + 1][2], s[2 * kb + 1][3], ph[3], pl[3]);
#pragma unroll
            for (int db = 0; db < 4; db++) {
                uint32_t addr = stg + KV_VH + (kb * 16 + (lane & 15)) * 144 + (db * 16 + (lane >> 4) * 8) * 2;
                uint32_t vfh[4], vfl[4];
                LDSM4T(vfh, addr);
                LDSM4T(vfl, addr + KV_KL);
                MMA_BF16(o[db * 2],     ph, vfh[0], vfh[1]);
                MMA_BF16(o[db * 2],     ph, vfl[0], vfl[1]);
                MMA_BF16(o[db * 2],     pl, vfh[0], vfh[1]);
                MMA_BF16(o[db * 2 + 1], ph, vfh[2], vfh[3]);
                MMA_BF16(o[db * 2 + 1], ph, vfl[2], vfl[3]);
                MMA_BF16(o[db * 2 + 1], pl, vfh[2], vfh[3]);
            }
        }
    }

    float inv0 = 1.f / l0, inv1 = 1.f / l1;
    int r0 = qbase + w * 16 + (lane >> 2);
    int c0c = (lane & 3) * 2;
#pragma unroll
    for (int db = 0; db < 8; db++) {
        int c = db * 8 + c0c;
        uint32_t hi, lo;
        size_t idx0 = ((size_t)bh * SS + r0) * DK + c;
        split2(o[db][0] * inv0, o[db][1] * inv0, hi, lo);
        ((uint32_t*)Oh)[idx0 >> 1] = hi;
        ((uint32_t*)Ol)[idx0 >> 1] = lo;
        size_t idx1 = ((size_t)bh * SS + r0 + 8) * DK + c;
        split2(o[db][2] * inv1, o[db][3] * inv1, hi, lo);
        ((uint32_t*)Oh)[idx1 >> 1] = hi;
        ((uint32_t*)Ol)[idx1 >> 1] = lo;
    }
}

// ---------------- LayerNorm (+ optional residual add, + optional split out) --
template<bool ADD, bool SPLIT>
__global__ __launch_bounds__(128)
void ln_kernel(const float* __restrict__ src, const float* __restrict__ gamma,
               const float* __restrict__ beta, float* __restrict__ xio,
               __nv_bfloat16* __restrict__ xh, __nv_bfloat16* __restrict__ xl, float eps) {
    int row = blockIdx.x;
    int t = threadIdx.x;
    int lane = t & 31, wid = t >> 5;
    const float4* sp = (const float4*)(src + (size_t)row * DD);
    float4 v = sp[t];

    __shared__ float red[4];
    __shared__ float bsum, bvar;

    float s = (v.x + v.y) + (v.z + v.w);
#pragma unroll
    for (int o = 16; o > 0; o >>= 1) s += __shfl_xor_sync(0xffffffffu, s, o);
    if (lane == 0) red[wid] = s;
    __syncthreads();
    if (t == 0) bsum = (red[0] + red[1]) + (red[2] + red[3]);
    __syncthreads();
    float mu = bsum * (1.f / DD);

    float dx = v.x - mu, dy = v.y - mu, dz = v.z - mu, dw = v.w - mu;
    float s2 = (dx * dx + dy * dy) + (dz * dz + dw * dw);
#pragma unroll
    for (int o = 16; o > 0; o >>= 1) s2 += __shfl_xor_sync(0xffffffffu, s2, o);
    if (lane == 0) red[wid] = s2;
    __syncthreads();
    if (t == 0) bvar = (red[0] + red[1]) + (red[2] + red[3]);
    __syncthreads();
    float rstd = rsqrtf(bvar * (1.f / DD) + eps);

    int c = t * 4;
    float4 g = *(const float4*)(gamma + c);
    float4 b = *(const float4*)(beta + c);
    float4 o4;
    o4.x = dx * rstd * g.x + b.x;
    o4.y = dy * rstd * g.y + b.y;
    o4.z = dz * rstd * g.z + b.z;
    o4.w = dw * rstd * g.w + b.w;
    float4* xp = (float4*)(xio + (size_t)row * DD);
    if (ADD) {
        float4 xo = xp[t];
        o4.x += xo.x; o4.y += xo.y; o4.z += xo.z; o4.w += xo.w;
    }
    xp[t] = o4;
    if (SPLIT) {
        size_t pidx = ((size_t)row * DD + c) >> 1;
        uint32_t hi, lo;
        split2(o4.x, o4.y, hi, lo);
        ((uint32_t*)xh)[pidx] = hi; ((uint32_t*)xl)[pidx] = lo;
        split2(o4.z, o4.w, hi, lo);
        ((uint32_t*)xh)[pidx + 1] = hi; ((uint32_t*)xl)[pidx + 1] = lo;
    }
}

// ---------------- driver ----------------
extern "C" void kernel_launch(void* const* d_in, const int* in_sizes, int n_in,
                              void* d_out, int out_size) {
    const float* src  = (const float*)d_in[0];
    const float* Wq   = (const float*)d_in[1];
    const float* bq   = (const float*)d_in[2];
    const float* Wk   = (const float*)d_in[3];
    const float* bk   = (const float*)d_in[4];
    const float* Wv   = (const float*)d_in[5];
    const float* bv   = (const float*)d_in[6];
    const float* Wo   = (const float*)d_in[7];
    const float* bo   = (const float*)d_in[8];
    const float* ln1g = (const float*)d_in[9];
    const float* ln1b = (const float*)d_in[10];
    const float* W1   = (const float*)d_in[11];
    const float* b1   = (const float*)d_in[12];
    const float* W2   = (const float*)d_in[13];
    const float* b2   = (const float*)d_in[14];
    const float* ln2g = (const float*)d_in[15];
    const float* ln2b = (const float*)d_in[16];
    const float* lnfg = (const float*)d_in[17];
    const float* lnfb = (const float*)d_in[18];
    float* out = (float*)d_out;

    float *px, *pt;
    __nv_bfloat16 *xs, *qs, *ks, *vs, *os, *fs;
    __nv_bfloat16 *wqs, *wks, *wvs, *wos, *w1s, *w2s;
    cudaGetSymbolAddress((void**)&px, g_x);
    cudaGetSymbolAddress((void**)&pt, g_t);
    cudaGetSymbolAddress((void**)&xs, g_xs);
    cudaGetSymbolAddress((void**)&qs, g_qs);
    cudaGetSymbolAddress((void**)&ks, g_ks);
    cudaGetSymbolAddress((void**)&vs, g_vs);
    cudaGetSymbolAddress((void**)&os, g_os);
    cudaGetSymbolAddress((void**)&fs, g_fs);
    cudaGetSymbolAddress((void**)&wqs, g_wq_s);
    cudaGetSymbolAddress((void**)&wks, g_wk_s);
    cudaGetSymbolAddress((void**)&wvs, g_wv_s);
    cudaGetSymbolAddress((void**)&wos, g_wo_s);
    cudaGetSymbolAddress((void**)&w1s, g_w1_s);
    cudaGetSymbolAddress((void**)&w2s, g_w2_s);

    __nv_bfloat16 *xh = xs, *xl = xs + (size_t)NN * DD;
    __nv_bfloat16 *qh = qs, *ql = qs + (size_t)NN * DD;
    __nv_bfloat16 *kh = ks, *kl = ks + (size_t)NN * DD;
    __nv_bfloat16 *vh = vs, *vl = vs + (size_t)NN * DD;
    __nv_bfloat16 *oh = os, *ol = os + (size_t)NN * DD;
    __nv_bfloat16 *fh = fs, *fl = fs + (size_t)NN * DFF;

    cudaFuncSetAttribute(hmma_gemm<0,1,false>, cudaFuncAttributeMaxDynamicSharedMemorySize, SMEM_DYN);
    cudaFuncSetAttribute(hmma_gemm<1,0,false>, cudaFuncAttributeMaxDynamicSharedMemorySize, SMEM_DYN);
    cudaFuncSetAttribute(hmma_gemm<0,2,true >, cudaFuncAttributeMaxDynamicSharedMemorySize, SMEM_DYN);
    cudaFuncSetAttribute(hmma_gemm<0,0,false>, cudaFuncAttributeMaxDynamicSharedMemorySize, SMEM_DYN);
    cudaFuncSetAttribute(attn_hmma, cudaFuncAttributeMaxDynamicSharedMemorySize, ATT_SMEM);

    // launch 0: all weight splits in one kernel (also shifts ncu -s 5 window onto attn)
    split_all_kernel<<<2304, 256>>>(Wq, Wk, Wv, Wo, W1, W2, wqs, wks, wvs, wos, w1s, w2s);
    // launch 1
    add_pe_kernel<<<(NN * DD / 2 + 255) / 256, 256>>>(src, px, xh, xl);

    dim3 gProj(4, 32);    // N=512, M tiles of 256
    dim3 gFfn1(16, 32);   // N=2048
    dim3 gAttn(BB * HH, SS / 128);

    for (int l = 0; l < LAY; l++) {
        size_t ws_proj = (size_t)l * 4 * 8 * TILE_ELEMS;
        size_t ws_w1   = (size_t)l * 16 * 8 * TILE_ELEMS;
        size_t ws_w2   = (size_t)l * 4 * 32 * TILE_ELEMS;

        hmma_gemm<0,1,false><<<gProj, 256, SMEM_DYN>>>(xh, xl, wqs + ws_proj, bq + l * HH * DK,
                                                       nullptr, qh, ql, NN, DD, DD, 0.125f);
        hmma_gemm<0,1,false><<<gProj, 256, SMEM_DYN>>>(xh, xl, wks + ws_proj, bk + l * HH * DK,
                                                       nullptr, kh, kl, NN, DD, DD, 1.0f);
        hmma_gemm<0,1,false><<<gProj, 256, SMEM_DYN>>>(xh, xl, wvs + ws_proj, bv + l * HH * DK,
                                                       nullptr, vh, vl, NN, DD, DD, 1.0f);

        attn_hmma<<<gAttn, 256, ATT_SMEM>>>(qh, ql, kh, kl, vh, vl, oh, ol);

        hmma_gemm<1,0,false><<<gProj, 256, SMEM_DYN>>>(oh, ol, wos + ws_proj, bo + l * DD,
                                                       pt, nullptr, nullptr, NN, DD, DD, 1.0f);
        ln_kernel<true,true><<<NN, 128>>>(pt, ln1g + l * DD, ln1b + l * DD, px, xh, xl, 1e-5f);

        hmma_gemm<0,2,true ><<<gFfn1, 256, SMEM_DYN>>>(xh, xl, w1s + ws_w1, b1 + l * DFF,
                                                       nullptr, fh, fl, NN, DFF, DD, 1.0f);
        hmma_gemm<0,0,false><<<gProj, 256, SMEM_DYN>>>(fh, fl, w2s + ws_w2, b2 + l * DD,
                                                       pt, nullptr, nullptr, NN, DD, DFF, 1.0f);
        ln_kernel<true,true><<<NN, 128>>>(pt, ln2g + l * DD, ln2b + l * DD, px, xh, xl, 1e-5f);
    }

    ln_kernel<false,false><<<NN, 128>>>(px, lnfg, lnfb, out, nullptr, nullptr, 1e-6f);
}